// round 1
// baseline (speedup 1.0000x reference)
#include <cuda_runtime.h>
#include <math.h>

// Problem constants
#define BB 4
#define NH 8
#define BHD 32          // B*NH
#define HH 96
#define WW 96
#define CC 512
#define DD 64           // head dim
#define HW 9216         // H*W
#define SCALING 0.125f  // (512/8)^-0.5

// ---------------------------------------------------------------------------
// Scratch (device globals: allocation-free rule)
// t/f/g stored head-permuted, channel-last:  [bh][y][x][d]
// E logits: [bh][y][x][192]  (0..95 = row keys i over x-axis, 96..191 = col keys i over y-axis)
// O: column-attention partial output [bh][y][x][d]
// ---------------------------------------------------------------------------
__device__ float d_t[(size_t)BHD * HW * DD];
__device__ float d_f[(size_t)BHD * HW * DD];
__device__ float d_g[(size_t)BHD * HW * DD];
__device__ float d_E[(size_t)BHD * HW * 192];
__device__ float d_O[(size_t)BHD * HW * DD];

// ---------------------------------------------------------------------------
// Kernel 1: 1x1 conv as GEMM.
//   dst[bh][y][x][d] = (sum_c X[b][c][y][x] * W[o][c] + bias[o]) * scale
//   o = h*64 + d, bh = b*8 + h
// Block tile: 32 pixels x 128 outputs, K-chunk 32. 256 threads, each 2x8 acc.
// sel: 0 -> d_t, 1 -> d_f, 2 -> d_g
// ---------------------------------------------------------------------------
__global__ void __launch_bounds__(256) conv1x1_kernel(
    const float* __restrict__ X, const float* __restrict__ Wt,
    const float* __restrict__ bias, float scale, int sel)
{
    __shared__ float As[32][33];
    __shared__ float Bs[32][132];

    float* dst = (sel == 0) ? d_t : (sel == 1) ? d_f : d_g;

    const int t  = threadIdx.x;
    const int m0 = blockIdx.x * 32;       // pixel tile (32 | 96, so no row wrap)
    const int o0 = blockIdx.y * 128;      // output-channel tile

    const int b  = m0 / HW;
    const int rm = m0 % HW;
    const int y  = rm / WW;
    const int x0 = rm % WW;

    const int tx = t & 15;                // -> 8 outputs
    const int ty = t >> 4;                // -> 2 pixels

    float acc[2][8];
#pragma unroll
    for (int p = 0; p < 2; p++)
#pragma unroll
        for (int j = 0; j < 8; j++) acc[p][j] = 0.f;

    const int px_l = t & 31, kk_l = t >> 5;   // A load: px coalesced
    const int cc_l = t & 31, og_l = t >> 5;   // B load: c coalesced

    const float* xbase = X + (size_t)b * CC * HW + (size_t)y * WW + x0;

    for (int k0 = 0; k0 < CC; k0 += 32) {
#pragma unroll
        for (int r = 0; r < 4; r++) {
            int kk = kk_l + r * 8;
            As[kk][px_l] = xbase[(size_t)(k0 + kk) * HW + px_l];
        }
#pragma unroll
        for (int r = 0; r < 16; r++) {
            int oo = og_l + r * 8;
            Bs[cc_l][oo] = Wt[(size_t)(o0 + oo) * CC + k0 + cc_l];
        }
        __syncthreads();

#pragma unroll
        for (int kk = 0; kk < 32; kk++) {
            float a0 = As[kk][ty * 2];
            float a1 = As[kk][ty * 2 + 1];
            float4 b0 = *(const float4*)&Bs[kk][tx * 8];
            float4 b1 = *(const float4*)&Bs[kk][tx * 8 + 4];
            acc[0][0] += a0 * b0.x; acc[0][1] += a0 * b0.y;
            acc[0][2] += a0 * b0.z; acc[0][3] += a0 * b0.w;
            acc[0][4] += a0 * b1.x; acc[0][5] += a0 * b1.y;
            acc[0][6] += a0 * b1.z; acc[0][7] += a0 * b1.w;
            acc[1][0] += a1 * b0.x; acc[1][1] += a1 * b0.y;
            acc[1][2] += a1 * b0.z; acc[1][3] += a1 * b0.w;
            acc[1][4] += a1 * b1.x; acc[1][5] += a1 * b1.y;
            acc[1][6] += a1 * b1.z; acc[1][7] += a1 * b1.w;
        }
        __syncthreads();
    }

    // Epilogue: bias + scale, write permuted [bh][y][x][d]
    const int obase = o0 + tx * 8;            // 8 outputs, never cross 64-boundary
    const int h  = obase >> 6;
    const int d0 = obase & 63;
    float bb[8];
#pragma unroll
    for (int j = 0; j < 8; j++) bb[j] = bias[obase + j];

#pragma unroll
    for (int p = 0; p < 2; p++) {
        const int x = x0 + ty * 2 + p;
        float* dp = dst + (((size_t)(b * NH + h) * HH + y) * WW + x) * DD + d0;
        float4 v0, v1;
        v0.x = (acc[p][0] + bb[0]) * scale; v0.y = (acc[p][1] + bb[1]) * scale;
        v0.z = (acc[p][2] + bb[2]) * scale; v0.w = (acc[p][3] + bb[3]) * scale;
        v1.x = (acc[p][4] + bb[4]) * scale; v1.y = (acc[p][5] + bb[5]) * scale;
        v1.z = (acc[p][6] + bb[6]) * scale; v1.w = (acc[p][7] + bb[7]) * scale;
        *(float4*)dp       = v0;
        *(float4*)(dp + 4) = v1;
    }
}

// ---------------------------------------------------------------------------
// Kernel 2: row logits.  Block (y, bh).
//   E[bh][y][x][i] = sum_d t[bh][y][x][d] * f[bh][y][i][d]
// ---------------------------------------------------------------------------
__global__ void __launch_bounds__(256) erow_kernel()
{
    extern __shared__ float sm[];
    float (*ts)[68] = (float(*)[68])sm;              // [x][d]
    float (*fr)[68] = (float(*)[68])(sm + 96 * 68);  // [i][d]

    const int y   = blockIdx.x;
    const int bh  = blockIdx.y;
    const int tid = threadIdx.x;

    const float* tb = d_t + (size_t)(bh * HH + y) * WW * DD;
    const float* fb = d_f + (size_t)(bh * HH + y) * WW * DD;
    for (int idx = tid; idx < 96 * 16; idx += 256) {
        int r = idx >> 4, dq = idx & 15;
        *(float4*)&ts[r][dq * 4] = *(const float4*)&tb[r * 64 + dq * 4];
        *(float4*)&fr[r][dq * 4] = *(const float4*)&fb[r * 64 + dq * 4];
    }
    __syncthreads();

    float* Eb = d_E + (size_t)(bh * HH + y) * WW * 192;

    for (int t2 = tid; t2 < 48 * 48; t2 += 256) {
        const int x = (t2 / 48) * 2;
        const int i = (t2 % 48) * 2;
        float4 s00 = {0,0,0,0}, s01 = {0,0,0,0}, s10 = {0,0,0,0}, s11 = {0,0,0,0};
#pragma unroll
        for (int dq = 0; dq < 16; dq++) {
            float4 ta = *(float4*)&ts[x][dq * 4];
            float4 tc = *(float4*)&ts[x + 1][dq * 4];
            float4 fa = *(float4*)&fr[i][dq * 4];
            float4 fc = *(float4*)&fr[i + 1][dq * 4];
            s00.x += ta.x * fa.x; s00.y += ta.y * fa.y; s00.z += ta.z * fa.z; s00.w += ta.w * fa.w;
            s01.x += ta.x * fc.x; s01.y += ta.y * fc.y; s01.z += ta.z * fc.z; s01.w += ta.w * fc.w;
            s10.x += tc.x * fa.x; s10.y += tc.y * fa.y; s10.z += tc.z * fa.z; s10.w += tc.w * fa.w;
            s11.x += tc.x * fc.x; s11.y += tc.y * fc.y; s11.z += tc.z * fc.z; s11.w += tc.w * fc.w;
        }
        Eb[(size_t)x * 192 + i]           = s00.x + s00.y + s00.z + s00.w;
        Eb[(size_t)x * 192 + i + 1]       = s01.x + s01.y + s01.z + s01.w;
        Eb[(size_t)(x + 1) * 192 + i]     = s10.x + s10.y + s10.z + s10.w;
        Eb[(size_t)(x + 1) * 192 + i + 1] = s11.x + s11.y + s11.z + s11.w;
    }
}

// ---------------------------------------------------------------------------
// Kernel 3: column logits.  Block (x, bh).
//   E[bh][y][x][96+i] = sum_d t[bh][y][x][d] * f[bh][i][x][d], diag(i==y)->-inf
// ---------------------------------------------------------------------------
__global__ void __launch_bounds__(256) ecol_kernel()
{
    extern __shared__ float sm[];
    float (*tc)[68] = (float(*)[68])sm;              // [y][d]
    float (*fc)[68] = (float(*)[68])(sm + 96 * 68);  // [i][d]

    const int x   = blockIdx.x;
    const int bh  = blockIdx.y;
    const int tid = threadIdx.x;

    for (int idx = tid; idx < 96 * 16; idx += 256) {
        int r = idx >> 4, dq = idx & 15;
        size_t g = ((size_t)(bh * HH + r) * WW + x) * DD + dq * 4;
        *(float4*)&tc[r][dq * 4] = *(const float4*)&d_t[g];
        *(float4*)&fc[r][dq * 4] = *(const float4*)&d_f[g];
    }
    __syncthreads();

    for (int t2 = tid; t2 < 48 * 48; t2 += 256) {
        const int yv = (t2 / 48) * 2;
        const int i  = (t2 % 48) * 2;
        float4 s00 = {0,0,0,0}, s01 = {0,0,0,0}, s10 = {0,0,0,0}, s11 = {0,0,0,0};
#pragma unroll
        for (int dq = 0; dq < 16; dq++) {
            float4 ta = *(float4*)&tc[yv][dq * 4];
            float4 tb = *(float4*)&tc[yv + 1][dq * 4];
            float4 fa = *(float4*)&fc[i][dq * 4];
            float4 fb = *(float4*)&fc[i + 1][dq * 4];
            s00.x += ta.x * fa.x; s00.y += ta.y * fa.y; s00.z += ta.z * fa.z; s00.w += ta.w * fa.w;
            s01.x += ta.x * fb.x; s01.y += ta.y * fb.y; s01.z += ta.z * fb.z; s01.w += ta.w * fb.w;
            s10.x += tb.x * fa.x; s10.y += tb.y * fa.y; s10.z += tb.z * fa.z; s10.w += tb.w * fa.w;
            s11.x += tb.x * fb.x; s11.y += tb.y * fb.y; s11.z += tb.z * fb.z; s11.w += tb.w * fb.w;
        }
        float e00 = s00.x + s00.y + s00.z + s00.w;
        float e01 = s01.x + s01.y + s01.z + s01.w;
        float e10 = s10.x + s10.y + s10.z + s10.w;
        float e11 = s11.x + s11.y + s11.z + s11.w;
        if (i     == yv)     e00 = -INFINITY;
        if (i + 1 == yv)     e01 = -INFINITY;
        if (i     == yv + 1) e10 = -INFINITY;
        if (i + 1 == yv + 1) e11 = -INFINITY;
        size_t b0 = ((size_t)(bh * HH + yv) * WW + x) * 192 + 96 + i;
        size_t b1 = ((size_t)(bh * HH + yv + 1) * WW + x) * 192 + 96 + i;
        d_E[b0] = e00; d_E[b0 + 1] = e01;
        d_E[b1] = e10; d_E[b1 + 1] = e11;
    }
}

// Warp-per-row softmax over 192 logits held in Es[96][200].
__device__ __forceinline__ void softmax_rows(float (*Es)[200], int tid)
{
    const int w = tid >> 5, lane = tid & 31;
#pragma unroll 1
    for (int rr = 0; rr < 12; rr++) {
        const int r = w * 12 + rr;
        float m = -INFINITY;
#pragma unroll
        for (int k = 0; k < 6; k++) m = fmaxf(m, Es[r][lane + k * 32]);
#pragma unroll
        for (int off = 16; off; off >>= 1) m = fmaxf(m, __shfl_xor_sync(0xffffffffu, m, off));
        float s = 0.f;
        float ev[6];
#pragma unroll
        for (int k = 0; k < 6; k++) { ev[k] = __expf(Es[r][lane + k * 32] - m); s += ev[k]; }
#pragma unroll
        for (int off = 16; off; off >>= 1) s += __shfl_xor_sync(0xffffffffu, s, off);
        const float inv = 1.f / s;
#pragma unroll
        for (int k = 0; k < 6; k++) Es[r][lane + k * 32] = ev[k] * inv;
    }
}

// ---------------------------------------------------------------------------
// Kernel 4: column-attention output partial.  Block (x, bh).
//   O[bh][y][x][d] = sum_i a_col[y][i] * g[bh][i][x][d]
// (softmax over the full 192 computed here; identical computation repeats in K5)
// ---------------------------------------------------------------------------
__global__ void __launch_bounds__(256) colout_kernel()
{
    extern __shared__ float sm[];
    float (*Es)[200] = (float(*)[200])sm;               // [y][192]
    float (*gc)[68]  = (float(*)[68])(sm + 96 * 200);   // [i][d]

    const int x   = blockIdx.x;
    const int bh  = blockIdx.y;
    const int tid = threadIdx.x;

    for (int idx = tid; idx < 96 * 48; idx += 256) {
        int r = idx / 48, jq = idx % 48;
        *(float4*)&Es[r][jq * 4] =
            *(const float4*)&d_E[((size_t)(bh * HH + r) * WW + x) * 192 + jq * 4];
    }
    for (int idx = tid; idx < 96 * 16; idx += 256) {
        int r = idx >> 4, dq = idx & 15;
        *(float4*)&gc[r][dq * 4] =
            *(const float4*)&d_g[((size_t)(bh * HH + r) * WW + x) * DD + dq * 4];
    }
    __syncthreads();

    softmax_rows(Es, tid);
    __syncthreads();

    for (int o4 = tid; o4 < 96 * 16; o4 += 256) {
        const int yv = o4 >> 4;
        const int dq = o4 & 15;
        float4 acc = {0,0,0,0};
#pragma unroll 4
        for (int i = 0; i < 96; i++) {
            float a = Es[yv][96 + i];
            float4 gv = *(float4*)&gc[i][dq * 4];
            acc.x += a * gv.x; acc.y += a * gv.y;
            acc.z += a * gv.z; acc.w += a * gv.w;
        }
        *(float4*)&d_O[((size_t)(bh * HH + yv) * WW + x) * DD + dq * 4] = acc;
    }
}

// ---------------------------------------------------------------------------
// Kernel 5: row-attention output + combine + residual.  Block (y, bh).
//   out[b][h*64+d][y][x] = gamma*( sum_i a_row[x][i]*g[bh][y][i][d] + O[bh][y][x][d] ) + v
// ---------------------------------------------------------------------------
__global__ void __launch_bounds__(256) rowout_kernel(
    const float* __restrict__ v, const float* __restrict__ gamma,
    float* __restrict__ out)
{
    extern __shared__ float sm[];
    float (*Es)[200] = (float(*)[200])sm;               // [x][192]
    float (*gr)[68]  = (float(*)[68])(sm + 96 * 200);   // [i][d]

    const int y   = blockIdx.x;
    const int bh  = blockIdx.y;
    const int tid = threadIdx.x;

    const float* Eb = d_E + (size_t)(bh * HH + y) * WW * 192;
    for (int idx = tid; idx < 96 * 48; idx += 256) {
        int r = idx / 48, jq = idx % 48;
        *(float4*)&Es[r][jq * 4] = *(const float4*)&Eb[r * 192 + jq * 4];
    }
    const float* gb = d_g + (size_t)(bh * HH + y) * WW * DD;
    for (int idx = tid; idx < 96 * 16; idx += 256) {
        int r = idx >> 4, dq = idx & 15;
        *(float4*)&gr[r][dq * 4] = *(const float4*)&gb[r * 64 + dq * 4];
    }
    __syncthreads();

    softmax_rows(Es, tid);
    __syncthreads();

    const float gam = gamma[0];
    const int b = bh >> 3, h = bh & 7;
    const float* colp = d_O + (size_t)(bh * HH + y) * WW * DD;

    for (int o4 = tid; o4 < 96 * 16; o4 += 256) {
        const int x  = o4 % 96;
        const int dq = o4 / 96;
        float4 acc = {0,0,0,0};
#pragma unroll 4
        for (int i = 0; i < 96; i++) {
            float a = Es[x][i];
            float4 gv = *(float4*)&gr[i][dq * 4];
            acc.x += a * gv.x; acc.y += a * gv.y;
            acc.z += a * gv.z; acc.w += a * gv.w;
        }
        float4 cp = *(const float4*)&colp[(size_t)x * DD + dq * 4];
        const int c0 = h * 64 + dq * 4;
        size_t oa = (((size_t)(b * CC + c0)) * HH + y) * WW + x;
        out[oa]          = gam * (acc.x + cp.x) + v[oa];
        out[oa + HW]     = gam * (acc.y + cp.y) + v[oa + HW];
        out[oa + 2 * HW] = gam * (acc.z + cp.z) + v[oa + 2 * HW];
        out[oa + 3 * HW] = gam * (acc.w + cp.w) + v[oa + 3 * HW];
    }
}

// ---------------------------------------------------------------------------
extern "C" void kernel_launch(void* const* d_in, const int* in_sizes, int n_in,
                              void* d_out, int out_size)
{
    const float* q     = (const float*)d_in[0];
    const float* v     = (const float*)d_in[1];
    const float* Wq    = (const float*)d_in[2];
    const float* bq    = (const float*)d_in[3];
    const float* Wk    = (const float*)d_in[4];
    const float* bk    = (const float*)d_in[5];
    const float* Wv    = (const float*)d_in[6];
    const float* bv    = (const float*)d_in[7];
    const float* gamma = (const float*)d_in[8];
    float* out = (float*)d_out;

    const int smE  = 2 * 96 * 68 * 4;                  // 52224 B  (K2/K3)
    const int smO  = (96 * 200 + 96 * 68) * 4;         // 102912 B (K4/K5)
    cudaFuncSetAttribute(erow_kernel,   cudaFuncAttributeMaxDynamicSharedMemorySize, smE);
    cudaFuncSetAttribute(ecol_kernel,   cudaFuncAttributeMaxDynamicSharedMemorySize, smE);
    cudaFuncSetAttribute(colout_kernel, cudaFuncAttributeMaxDynamicSharedMemorySize, smO);
    cudaFuncSetAttribute(rowout_kernel, cudaFuncAttributeMaxDynamicSharedMemorySize, smO);

    dim3 gemmGrid(HW * BB / 32, 4);   // 1152 x 4
    conv1x1_kernel<<<gemmGrid, 256>>>(q, Wq, bq, SCALING, 0);  // t
    conv1x1_kernel<<<gemmGrid, 256>>>(q, Wk, bk, 1.0f,    1);  // f
    conv1x1_kernel<<<gemmGrid, 256>>>(v, Wv, bv, 1.0f,    2);  // g

    dim3 attnGrid(96, BHD);
    erow_kernel<<<attnGrid, 256, smE>>>();
    ecol_kernel<<<attnGrid, 256, smE>>>();
    colout_kernel<<<attnGrid, 256, smO>>>();
    rowout_kernel<<<attnGrid, 256, smO>>>(v, gamma, out);
}

// round 2
// speedup vs baseline: 1.9655x; 1.9655x over previous
#include <cuda_runtime.h>
#include <math.h>

#define BB 4
#define NH 8
#define BHD 32
#define HH 96
#define WW 96
#define CC 512
#define DD 64
#define HW 9216
#define SCALING 0.125f

typedef unsigned long long u64;

// Scratch device globals
__device__ float d_t[(size_t)BHD * HW * DD];
__device__ float d_f[(size_t)BHD * HW * DD];
__device__ float d_g[(size_t)BHD * HW * DD];
__device__ float d_E[(size_t)BHD * HW * 192];
__device__ float d_O[(size_t)BHD * HW * DD];

// ---- packed f32x2 helpers -------------------------------------------------
__device__ __forceinline__ u64 dup2(float x) {
    u64 r;
    asm("mov.b64 %0, {%1, %1};" : "=l"(r) : "r"(__float_as_uint(x)));
    return r;
}
__device__ __forceinline__ void ffma2(u64& d, u64 a, u64 b) {
    asm("fma.rn.f32x2 %0, %1, %2, %0;" : "+l"(d) : "l"(a), "l"(b));
}
__device__ __forceinline__ float lo2(u64 v) { return __uint_as_float((unsigned)v); }
__device__ __forceinline__ float hi2(u64 v) { return __uint_as_float((unsigned)(v >> 32)); }

// ---------------------------------------------------------------------------
// Kernel 1: 1x1 conv GEMM. Block tile 128 px x 128 out, K-chunk 16.
// 256 threads (16x16): thread tile = 8 px (contiguous, packed in f32x2 pairs)
// x 8 outputs (strided by 16 for conflict-free scalar b reads).
// ---------------------------------------------------------------------------
__global__ void __launch_bounds__(256) conv1x1_kernel(
    const float* __restrict__ X, const float* __restrict__ Wt,
    const float* __restrict__ bias, float scale, int sel)
{
    __shared__ float As[16][128];
    __shared__ float Bs[16][132];

    float* dst = (sel == 0) ? d_t : (sel == 1) ? d_f : d_g;

    const int t  = threadIdx.x;
    const int m0 = blockIdx.x * 128;       // 128 | 9216 -> never crosses batch
    const int o0 = blockIdx.y * 128;

    const int b    = m0 / HW;
    const int pix0 = m0 % HW;

    // global load mappings
    const int akk = t >> 4, apq = t & 15;          // A: row kk, float4 col pq (+16)
    const int boo = t >> 2, bcq = t & 3;           // B: out row oo (+64), c-quad cq
    const float* aptr = X + (size_t)b * CC * HW + pix0 + (size_t)akk * HW + apq * 4;
    const float* bptr = Wt + (size_t)(o0 + boo) * CC + bcq * 4;

    const int tx = t & 15;     // output lane: o = o0 + tx + 16*j
    const int ty = t >> 4;     // pixel sub-tile: px = ty*8 .. ty*8+7

    u64 acc[4][8];
#pragma unroll
    for (int p = 0; p < 4; p++)
#pragma unroll
        for (int j = 0; j < 8; j++) acc[p][j] = 0ull;

    float4 aR0, aR1, bR0, bR1;
    aR0 = *(const float4*)(aptr);
    aR1 = *(const float4*)(aptr + 64);
    bR0 = *(const float4*)(bptr);
    bR1 = *(const float4*)(bptr + (size_t)64 * CC);

    for (int k0 = 0; k0 < CC; k0 += 16) {
        // store staged chunk
        *(float4*)&As[akk][apq * 4]      = aR0;
        *(float4*)&As[akk][apq * 4 + 64] = aR1;
        Bs[bcq * 4 + 0][boo] = bR0.x;  Bs[bcq * 4 + 1][boo] = bR0.y;
        Bs[bcq * 4 + 2][boo] = bR0.z;  Bs[bcq * 4 + 3][boo] = bR0.w;
        Bs[bcq * 4 + 0][boo + 64] = bR1.x;  Bs[bcq * 4 + 1][boo + 64] = bR1.y;
        Bs[bcq * 4 + 2][boo + 64] = bR1.z;  Bs[bcq * 4 + 3][boo + 64] = bR1.w;
        __syncthreads();

        if (k0 + 16 < CC) {
            aR0 = *(const float4*)(aptr + (size_t)(k0 + 16) * HW);
            aR1 = *(const float4*)(aptr + (size_t)(k0 + 16) * HW + 64);
            bR0 = *(const float4*)(bptr + k0 + 16);
            bR1 = *(const float4*)(bptr + (size_t)64 * CC + k0 + 16);
        }

#pragma unroll
        for (int kk = 0; kk < 16; kk++) {
            ulonglong2 aP0 = *(const ulonglong2*)&As[kk][ty * 8];
            ulonglong2 aP1 = *(const ulonglong2*)&As[kk][ty * 8 + 4];
            u64 ap[4] = {aP0.x, aP0.y, aP1.x, aP1.y};
            u64 bd[8];
#pragma unroll
            for (int j = 0; j < 8; j++) bd[j] = dup2(Bs[kk][tx + 16 * j]);
#pragma unroll
            for (int p = 0; p < 4; p++)
#pragma unroll
                for (int j = 0; j < 8; j++) ffma2(acc[p][j], ap[p], bd[j]);
        }
        __syncthreads();
    }

    // epilogue: bias+scale, write permuted [bh][pp][d]
    float bb[8];
#pragma unroll
    for (int j = 0; j < 8; j++) bb[j] = bias[o0 + tx + 16 * j];

#pragma unroll
    for (int p = 0; p < 8; p++) {
        const int pp = pix0 + ty * 8 + p;
#pragma unroll
        for (int j = 0; j < 8; j++) {
            const int o = o0 + tx + 16 * j;
            const int h = o >> 6, d = o & 63;
            float val = (p & 1) ? hi2(acc[p >> 1][j]) : lo2(acc[p >> 1][j]);
            dst[((size_t)(b * NH + h) * HW + pp) * DD + d] = (val + bb[j]) * scale;
        }
    }
}

// ---------------------------------------------------------------------------
// Kernel 2: row logits. Block (y, bh). 16x16 threads, 6x6 tile, f32x2.
//   E[bh][y][x][i] = sum_d t[bh][y][x][d] * f[bh][y][i][d]
// ---------------------------------------------------------------------------
__global__ void __launch_bounds__(256) erow_kernel()
{
    extern __shared__ float sm[];
    float (*ts)[68] = (float(*)[68])sm;
    float (*fr)[68] = (float(*)[68])(sm + 96 * 68);

    const int y   = blockIdx.x;
    const int bh  = blockIdx.y;
    const int tid = threadIdx.x;

    const float* tb = d_t + (size_t)(bh * HH + y) * WW * DD;
    const float* fb = d_f + (size_t)(bh * HH + y) * WW * DD;
    for (int idx = tid; idx < 96 * 16; idx += 256) {
        int r = idx >> 4, dq = idx & 15;
        *(float4*)&ts[r][dq * 4] = *(const float4*)&tb[r * 64 + dq * 4];
        *(float4*)&fr[r][dq * 4] = *(const float4*)&fb[r * 64 + dq * 4];
    }
    __syncthreads();

    const int x0 = (tid >> 4) * 6;
    const int i0 = (tid & 15) * 6;

    u64 acc[6][6];
#pragma unroll
    for (int p = 0; p < 6; p++)
#pragma unroll
        for (int q = 0; q < 6; q++) acc[p][q] = 0ull;

#pragma unroll 4
    for (int ds = 0; ds < 16; ds++) {
        ulonglong2 av[6], bv[6];
#pragma unroll
        for (int p = 0; p < 6; p++) av[p] = *(const ulonglong2*)&ts[x0 + p][ds * 4];
#pragma unroll
        for (int q = 0; q < 6; q++) bv[q] = *(const ulonglong2*)&fr[i0 + q][ds * 4];
#pragma unroll
        for (int p = 0; p < 6; p++)
#pragma unroll
            for (int q = 0; q < 6; q++) {
                ffma2(acc[p][q], av[p].x, bv[q].x);
                ffma2(acc[p][q], av[p].y, bv[q].y);
            }
    }

    float* Eb = d_E + (size_t)(bh * HH + y) * WW * 192;
#pragma unroll
    for (int p = 0; p < 6; p++)
#pragma unroll
        for (int q = 0; q < 6; q++)
            Eb[(size_t)(x0 + p) * 192 + (i0 + q)] = lo2(acc[p][q]) + hi2(acc[p][q]);
}

// ---------------------------------------------------------------------------
// Kernel 3: column logits. Block (x, bh). Same 6x6 f32x2 tiling + diag mask.
// ---------------------------------------------------------------------------
__global__ void __launch_bounds__(256) ecol_kernel()
{
    extern __shared__ float sm[];
    float (*tc)[68] = (float(*)[68])sm;
    float (*fc)[68] = (float(*)[68])(sm + 96 * 68);

    const int x   = blockIdx.x;
    const int bh  = blockIdx.y;
    const int tid = threadIdx.x;

    for (int idx = tid; idx < 96 * 16; idx += 256) {
        int r = idx >> 4, dq = idx & 15;
        size_t g = ((size_t)(bh * HH + r) * WW + x) * DD + dq * 4;
        *(float4*)&tc[r][dq * 4] = *(const float4*)&d_t[g];
        *(float4*)&fc[r][dq * 4] = *(const float4*)&d_f[g];
    }
    __syncthreads();

    const int y0 = (tid >> 4) * 6;
    const int i0 = (tid & 15) * 6;

    u64 acc[6][6];
#pragma unroll
    for (int p = 0; p < 6; p++)
#pragma unroll
        for (int q = 0; q < 6; q++) acc[p][q] = 0ull;

#pragma unroll 4
    for (int ds = 0; ds < 16; ds++) {
        ulonglong2 av[6], bv[6];
#pragma unroll
        for (int p = 0; p < 6; p++) av[p] = *(const ulonglong2*)&tc[y0 + p][ds * 4];
#pragma unroll
        for (int q = 0; q < 6; q++) bv[q] = *(const ulonglong2*)&fc[i0 + q][ds * 4];
#pragma unroll
        for (int p = 0; p < 6; p++)
#pragma unroll
            for (int q = 0; q < 6; q++) {
                ffma2(acc[p][q], av[p].x, bv[q].x);
                ffma2(acc[p][q], av[p].y, bv[q].y);
            }
    }

#pragma unroll
    for (int p = 0; p < 6; p++) {
        size_t base = ((size_t)(bh * HH + y0 + p) * WW + x) * 192 + 96;
#pragma unroll
        for (int q = 0; q < 6; q++) {
            float e = lo2(acc[p][q]) + hi2(acc[p][q]);
            if (i0 + q == y0 + p) e = -INFINITY;
            d_E[base + i0 + q] = e;
        }
    }
}

// Warp-per-row softmax over 192 logits held in Es[96][200].
__device__ __forceinline__ void softmax_rows(float (*Es)[200], int tid)
{
    const int w = tid >> 5, lane = tid & 31;
#pragma unroll 1
    for (int rr = 0; rr < 12; rr++) {
        const int r = w * 12 + rr;
        float m = -INFINITY;
#pragma unroll
        for (int k = 0; k < 6; k++) m = fmaxf(m, Es[r][lane + k * 32]);
#pragma unroll
        for (int off = 16; off; off >>= 1) m = fmaxf(m, __shfl_xor_sync(0xffffffffu, m, off));
        float s = 0.f;
        float ev[6];
#pragma unroll
        for (int k = 0; k < 6; k++) { ev[k] = __expf(Es[r][lane + k * 32] - m); s += ev[k]; }
#pragma unroll
        for (int off = 16; off; off >>= 1) s += __shfl_xor_sync(0xffffffffu, s, off);
        const float inv = 1.f / s;
#pragma unroll
        for (int k = 0; k < 6; k++) Es[r][lane + k * 32] = ev[k] * inv;
    }
}

// ---------------------------------------------------------------------------
// Kernel 4: column-attention output partial. Block (x, bh).
// ---------------------------------------------------------------------------
__global__ void __launch_bounds__(256) colout_kernel()
{
    extern __shared__ float sm[];
    float (*Es)[200] = (float(*)[200])sm;
    float (*gc)[68]  = (float(*)[68])(sm + 96 * 200);

    const int x   = blockIdx.x;
    const int bh  = blockIdx.y;
    const int tid = threadIdx.x;

    for (int idx = tid; idx < 96 * 48; idx += 256) {
        int r = idx / 48, jq = idx % 48;
        *(float4*)&Es[r][jq * 4] =
            *(const float4*)&d_E[((size_t)(bh * HH + r) * WW + x) * 192 + jq * 4];
    }
    for (int idx = tid; idx < 96 * 16; idx += 256) {
        int r = idx >> 4, dq = idx & 15;
        *(float4*)&gc[r][dq * 4] =
            *(const float4*)&d_g[((size_t)(bh * HH + r) * WW + x) * DD + dq * 4];
    }
    __syncthreads();

    softmax_rows(Es, tid);
    __syncthreads();

    for (int it = tid; it < 768; it += 256) {
        const int dq = it & 15;
        const int y0 = (it >> 4) * 2;
        float4 a0 = {0,0,0,0}, a1 = {0,0,0,0};
        for (int i = 0; i < 96; i += 4) {
            float4 w0 = *(const float4*)&Es[y0][96 + i];
            float4 w1 = *(const float4*)&Es[y0 + 1][96 + i];
            float4 g0 = *(const float4*)&gc[i][dq * 4];
            float4 g1 = *(const float4*)&gc[i + 1][dq * 4];
            float4 g2 = *(const float4*)&gc[i + 2][dq * 4];
            float4 g3 = *(const float4*)&gc[i + 3][dq * 4];
            a0.x += w0.x * g0.x + w0.y * g1.x + w0.z * g2.x + w0.w * g3.x;
            a0.y += w0.x * g0.y + w0.y * g1.y + w0.z * g2.y + w0.w * g3.y;
            a0.z += w0.x * g0.z + w0.y * g1.z + w0.z * g2.z + w0.w * g3.z;
            a0.w += w0.x * g0.w + w0.y * g1.w + w0.z * g2.w + w0.w * g3.w;
            a1.x += w1.x * g0.x + w1.y * g1.x + w1.z * g2.x + w1.w * g3.x;
            a1.y += w1.x * g0.y + w1.y * g1.y + w1.z * g2.y + w1.w * g3.y;
            a1.z += w1.x * g0.z + w1.y * g1.z + w1.z * g2.z + w1.w * g3.z;
            a1.w += w1.x * g0.w + w1.y * g1.w + w1.z * g2.w + w1.w * g3.w;
        }
        *(float4*)&d_O[((size_t)(bh * HH + y0) * WW + x) * DD + dq * 4]     = a0;
        *(float4*)&d_O[((size_t)(bh * HH + y0 + 1) * WW + x) * DD + dq * 4] = a1;
    }
}

// ---------------------------------------------------------------------------
// Kernel 5: row-attention output + combine + residual. Block (y, bh).
// ---------------------------------------------------------------------------
__global__ void __launch_bounds__(256) rowout_kernel(
    const float* __restrict__ v, const float* __restrict__ gamma,
    float* __restrict__ out)
{
    extern __shared__ float sm[];
    float (*Es)[200] = (float(*)[200])sm;
    float (*gr)[68]  = (float(*)[68])(sm + 96 * 200);

    const int y   = blockIdx.x;
    const int bh  = blockIdx.y;
    const int tid = threadIdx.x;

    const float* Eb = d_E + (size_t)(bh * HH + y) * WW * 192;
    for (int idx = tid; idx < 96 * 48; idx += 256) {
        int r = idx / 48, jq = idx % 48;
        *(float4*)&Es[r][jq * 4] = *(const float4*)&Eb[r * 192 + jq * 4];
    }
    const float* gb = d_g + (size_t)(bh * HH + y) * WW * DD;
    for (int idx = tid; idx < 96 * 16; idx += 256) {
        int r = idx >> 4, dq = idx & 15;
        *(float4*)&gr[r][dq * 4] = *(const float4*)&gb[r * 64 + dq * 4];
    }
    __syncthreads();

    softmax_rows(Es, tid);
    __syncthreads();

    const float gam = gamma[0];
    const int b = bh >> 3, h = bh & 7;
    const float* colp = d_O + (size_t)(bh * HH + y) * WW * DD;

    for (int it = tid; it < 768; it += 256) {
        const int xp = it % 48;
        const int dq = it / 48;
        const int x0 = xp * 2;
        float4 a0 = {0,0,0,0}, a1 = {0,0,0,0};
        for (int i = 0; i < 96; i += 4) {
            float4 w0 = *(const float4*)&Es[x0][i];
            float4 w1 = *(const float4*)&Es[x0 + 1][i];
            float4 g0 = *(const float4*)&gr[i][dq * 4];
            float4 g1 = *(const float4*)&gr[i + 1][dq * 4];
            float4 g2 = *(const float4*)&gr[i + 2][dq * 4];
            float4 g3 = *(const float4*)&gr[i + 3][dq * 4];
            a0.x += w0.x * g0.x + w0.y * g1.x + w0.z * g2.x + w0.w * g3.x;
            a0.y += w0.x * g0.y + w0.y * g1.y + w0.z * g2.y + w0.w * g3.y;
            a0.z += w0.x * g0.z + w0.y * g1.z + w0.z * g2.z + w0.w * g3.z;
            a0.w += w0.x * g0.w + w0.y * g1.w + w0.z * g2.w + w0.w * g3.w;
            a1.x += w1.x * g0.x + w1.y * g1.x + w1.z * g2.x + w1.w * g3.x;
            a1.y += w1.x * g0.y + w1.y * g1.y + w1.z * g2.y + w1.w * g3.y;
            a1.z += w1.x * g0.z + w1.y * g1.z + w1.z * g2.z + w1.w * g3.z;
            a1.w += w1.x * g0.w + w1.y * g1.w + w1.z * g2.w + w1.w * g3.w;
        }
        float4 cp0 = *(const float4*)&colp[(size_t)x0 * DD + dq * 4];
        float4 cp1 = *(const float4*)&colp[(size_t)(x0 + 1) * DD + dq * 4];
        const int c0 = h * 64 + dq * 4;
        size_t oa = (((size_t)(b * CC + c0)) * HH + y) * WW + x0;

        float2 s0, s1, s2, s3;
        s0.x = gam * (a0.x + cp0.x) + v[oa];
        s0.y = gam * (a1.x + cp1.x) + v[oa + 1];
        s1.x = gam * (a0.y + cp0.y) + v[oa + HW];
        s1.y = gam * (a1.y + cp1.y) + v[oa + HW + 1];
        s2.x = gam * (a0.z + cp0.z) + v[oa + 2 * HW];
        s2.y = gam * (a1.z + cp1.z) + v[oa + 2 * HW + 1];
        s3.x = gam * (a0.w + cp0.w) + v[oa + 3 * HW];
        s3.y = gam * (a1.w + cp1.w) + v[oa + 3 * HW + 1];
        *(float2*)&out[oa]          = s0;
        *(float2*)&out[oa + HW]     = s1;
        *(float2*)&out[oa + 2 * HW] = s2;
        *(float2*)&out[oa + 3 * HW] = s3;
    }
}

// ---------------------------------------------------------------------------
extern "C" void kernel_launch(void* const* d_in, const int* in_sizes, int n_in,
                              void* d_out, int out_size)
{
    const float* q     = (const float*)d_in[0];
    const float* v     = (const float*)d_in[1];
    const float* Wq    = (const float*)d_in[2];
    const float* bq    = (const float*)d_in[3];
    const float* Wk    = (const float*)d_in[4];
    const float* bk    = (const float*)d_in[5];
    const float* Wv    = (const float*)d_in[6];
    const float* bv    = (const float*)d_in[7];
    const float* gamma = (const float*)d_in[8];
    float* out = (float*)d_out;

    const int smE = 2 * 96 * 68 * 4;
    const int smO = (96 * 200 + 96 * 68) * 4;
    cudaFuncSetAttribute(erow_kernel,   cudaFuncAttributeMaxDynamicSharedMemorySize, smE);
    cudaFuncSetAttribute(ecol_kernel,   cudaFuncAttributeMaxDynamicSharedMemorySize, smE);
    cudaFuncSetAttribute(colout_kernel, cudaFuncAttributeMaxDynamicSharedMemorySize, smO);
    cudaFuncSetAttribute(rowout_kernel, cudaFuncAttributeMaxDynamicSharedMemorySize, smO);

    dim3 gemmGrid(HW * BB / 128, 4);   // 288 x 4
    conv1x1_kernel<<<gemmGrid, 256>>>(q, Wq, bq, SCALING, 0);  // t
    conv1x1_kernel<<<gemmGrid, 256>>>(q, Wk, bk, 1.0f,    1);  // f
    conv1x1_kernel<<<gemmGrid, 256>>>(v, Wv, bv, 1.0f,    2);  // g

    dim3 attnGrid(96, BHD);
    erow_kernel<<<attnGrid, 256, smE>>>();
    ecol_kernel<<<attnGrid, 256, smE>>>();
    colout_kernel<<<attnGrid, 256, smO>>>();
    rowout_kernel<<<attnGrid, 256, smO>>>(v, gamma, out);
}

// round 4
// speedup vs baseline: 2.8221x; 1.4359x over previous
#include <cuda_runtime.h>
#include <cuda_bf16.h>
#include <math.h>
#include <cstdint>

#define BB 4
#define NH 8
#define BHD 32
#define HH 96
#define WW 96
#define CC 512
#define DD 64
#define HW 9216
#define MTOT (BB * HW)      // 36864
#define SCALING 0.125f

typedef unsigned long long u64;

// ---------------------------------------------------------------------------
// Device-global scratch
// ---------------------------------------------------------------------------
__device__ float d_t[(size_t)BHD * HW * DD];
__device__ float d_f[(size_t)BHD * HW * DD];
__device__ float d_g[(size_t)BHD * HW * DD];
__device__ float d_E[(size_t)BHD * HW * 192];
__device__ float d_O[(size_t)BHD * HW * DD];
// bf16 hi/lo split operands, K-major [m][c]
__device__ __nv_bfloat16 d_Aq_hi[(size_t)MTOT * CC];
__device__ __nv_bfloat16 d_Aq_lo[(size_t)MTOT * CC];
__device__ __nv_bfloat16 d_Av_hi[(size_t)MTOT * CC];
__device__ __nv_bfloat16 d_Av_lo[(size_t)MTOT * CC];
__device__ __nv_bfloat16 d_Wh[3 * CC * CC];
__device__ __nv_bfloat16 d_Wl[3 * CC * CC];

// ---------------------------------------------------------------------------
// Warp-MMA helpers (generic PTX: sm_80+ features only)
// ---------------------------------------------------------------------------
__device__ __forceinline__ uint32_t smem_u32(const void* p) {
    uint32_t a;
    asm("{ .reg .u64 t; cvta.to.shared.u64 t, %1; cvt.u32.u64 %0, t; }" : "=r"(a) : "l"(p));
    return a;
}
__device__ __forceinline__ void ldmx4(uint32_t* r, uint32_t addr) {
    asm volatile("ldmatrix.sync.aligned.m8n8.x4.shared.b16 {%0,%1,%2,%3}, [%4];"
        : "=r"(r[0]), "=r"(r[1]), "=r"(r[2]), "=r"(r[3]) : "r"(addr));
}
__device__ __forceinline__ void mma16816(float* c, const uint32_t* a,
                                         uint32_t b0, uint32_t b1) {
    asm volatile(
        "mma.sync.aligned.m16n8k16.row.col.f32.bf16.bf16.f32 "
        "{%0,%1,%2,%3}, {%4,%5,%6,%7}, {%8,%9}, {%0,%1,%2,%3};"
        : "+f"(c[0]), "+f"(c[1]), "+f"(c[2]), "+f"(c[3])
        : "r"(a[0]), "r"(a[1]), "r"(a[2]), "r"(a[3]), "r"(b0), "r"(b1));
}

// ---- packed f32x2 helpers (attention kernels) ------------------------------
__device__ __forceinline__ u64 dup2(float x) {
    u64 r;
    asm("mov.b64 %0, {%1, %1};" : "=l"(r) : "r"(__float_as_uint(x)));
    return r;
}
__device__ __forceinline__ void ffma2(u64& d, u64 a, u64 b) {
    asm("fma.rn.f32x2 %0, %1, %2, %0;" : "+l"(d) : "l"(a), "l"(b));
}
__device__ __forceinline__ float lo2(u64 v) { return __uint_as_float((unsigned)v); }
__device__ __forceinline__ float hi2(u64 v) { return __uint_as_float((unsigned)(v >> 32)); }

// ---------------------------------------------------------------------------
// Prepass A: transpose + bf16 split  X[b][c][px] (fp32) -> A_hi/A_lo [m][c]
// ---------------------------------------------------------------------------
__global__ void __launch_bounds__(256) splitX_kernel(
    const float* __restrict__ X, __nv_bfloat16* __restrict__ hi,
    __nv_bfloat16* __restrict__ lo)
{
    __shared__ float tile[32][33];
    const int t   = threadIdx.x;
    const int px0 = blockIdx.x * 32;
    const int c0  = blockIdx.y * 32;
    const int b   = blockIdx.z;

#pragma unroll
    for (int r = 0; r < 4; r++) {
        int ci = (t >> 5) + r * 8, pj = t & 31;
        tile[ci][pj] = X[((size_t)b * CC + c0 + ci) * HW + px0 + pj];
    }
    __syncthreads();
#pragma unroll
    for (int r = 0; r < 4; r++) {
        int pj = (t >> 5) + r * 8, ci = t & 31;
        float v = tile[ci][pj];
        __nv_bfloat16 h = __float2bfloat16(v);
        float rem = v - __bfloat162float(h);
        size_t idx = ((size_t)b * HW + px0 + pj) * CC + c0 + ci;
        hi[idx] = h;
        lo[idx] = __float2bfloat16(rem);
    }
}

// Prepass B: split weight matrices (already K-major)
__global__ void __launch_bounds__(256) splitW_kernel(
    const float* __restrict__ W, __nv_bfloat16* __restrict__ hi,
    __nv_bfloat16* __restrict__ lo)
{
    int i = blockIdx.x * 256 + threadIdx.x;
    if (i < CC * CC) {
        float v = W[i];
        __nv_bfloat16 h = __float2bfloat16(v);
        hi[i] = h;
        lo[i] = __float2bfloat16(v - __bfloat162float(h));
    }
}

// ---------------------------------------------------------------------------
// Conv GEMM on mma.sync (bf16 hi/lo, 3 MMAs, fp32 accum).
// Block tile 128(m) x 128(n), K chunk 32. 8 warps, warp tile 32(m) x 64(n).
// SMEM rows padded to 40 bf16 (80B) -> ldmatrix conflict-free.
// ---------------------------------------------------------------------------
#define KPAD 40

__global__ void __launch_bounds__(256) conv_wmma_kernel(
    const __nv_bfloat16* __restrict__ Ah, const __nv_bfloat16* __restrict__ Al,
    const __nv_bfloat16* __restrict__ Bh, const __nv_bfloat16* __restrict__ Bl,
    const float* __restrict__ bias, float scale, int sel)
{
    __shared__ __align__(16) __nv_bfloat16 sA[2][128][KPAD];
    __shared__ __align__(16) __nv_bfloat16 sB[2][128][KPAD];

    float* dst = (sel == 0) ? d_t : (sel == 1) ? d_f : d_g;

    const int tid  = threadIdx.x;
    const int lane = tid & 31;
    const int warp = tid >> 5;
    const int wm   = warp & 3;     // m sub-block (32 rows)
    const int wn   = warp >> 2;    // n sub-block (64 cols)

    const int M0 = blockIdx.x * 128;
    const int o0 = blockIdx.y * 128;

    const uint32_t sAb = smem_u32(sA);
    const uint32_t sBb = smem_u32(sB);

    float acc[2][8][4];
#pragma unroll
    for (int mi = 0; mi < 2; mi++)
#pragma unroll
        for (int nf = 0; nf < 8; nf++)
#pragma unroll
            for (int k = 0; k < 4; k++) acc[mi][nf][k] = 0.f;

    // per-thread ldmatrix source coords (shared by A and B patterns)
    const int lrow = lane & 15;
    const int lcol = (lane >> 4) * 8;

    for (int ch = 0; ch < 16; ch++) {
        const int k0 = ch * 32;

        // --- stage chunk ---
#pragma unroll
        for (int r = 0; r < 2; r++) {
            int i   = tid + r * 256;
            int row = i >> 2, q = i & 3;
            const size_t ga = (size_t)(M0 + row) * CC + k0 + q * 8;
            const size_t gb = (size_t)(o0 + row) * CC + k0 + q * 8;
            *(uint4*)&sA[0][row][q * 8] = *(const uint4*)(Ah + ga);
            *(uint4*)&sA[1][row][q * 8] = *(const uint4*)(Al + ga);
            *(uint4*)&sB[0][row][q * 8] = *(const uint4*)(Bh + gb);
            *(uint4*)&sB[1][row][q * 8] = *(const uint4*)(Bl + gb);
        }
        __syncthreads();

#pragma unroll
        for (int ks = 0; ks < 2; ks++) {
            const int kc = ks * 16 + lcol;

            // A fragments: [hi/lo][mi][4]
            uint32_t a[2][2][4];
#pragma unroll
            for (int s = 0; s < 2; s++)
#pragma unroll
                for (int mi = 0; mi < 2; mi++) {
                    uint32_t off = ((s * 128 + wm * 32 + mi * 16 + lrow) * KPAD + kc) * 2;
                    ldmx4(a[s][mi], sAb + off);
                }

#pragma unroll
            for (int np = 0; np < 4; np++) {
                uint32_t bh[4], bl[4];
                {
                    uint32_t offh = ((0 * 128 + wn * 64 + np * 16 + lrow) * KPAD + kc) * 2;
                    uint32_t offl = ((1 * 128 + wn * 64 + np * 16 + lrow) * KPAD + kc) * 2;
                    ldmx4(bh, sBb + offh);
                    ldmx4(bl, sBb + offl);
                }
#pragma unroll
                for (int mi = 0; mi < 2; mi++)
#pragma unroll
                    for (int hf = 0; hf < 2; hf++) {
                        const int nf = np * 2 + hf;
                        mma16816(acc[mi][nf], a[0][mi], bh[hf], bh[2 + hf]);
                        mma16816(acc[mi][nf], a[0][mi], bl[hf], bl[2 + hf]);
                        mma16816(acc[mi][nf], a[1][mi], bh[hf], bh[2 + hf]);
                    }
            }
        }
        __syncthreads();
    }

    // --- epilogue: bias + scale, write permuted [bh][pp][d] ---
#pragma unroll
    for (int mi = 0; mi < 2; mi++) {
        const int m  = M0 + wm * 32 + mi * 16 + (lane >> 2);
        const int b  = m / HW;
        const int pp = m % HW;
#pragma unroll
        for (int nf = 0; nf < 8; nf++) {
            const int o = o0 + wn * 64 + nf * 8 + (lane & 3) * 2;
            const int h = o >> 6, d = o & 63;
            const float b0 = bias[o], b1 = bias[o + 1];
            float2 r0, r1;
            r0.x = (acc[mi][nf][0] + b0) * scale;
            r0.y = (acc[mi][nf][1] + b1) * scale;
            r1.x = (acc[mi][nf][2] + b0) * scale;
            r1.y = (acc[mi][nf][3] + b1) * scale;
            float* base = dst + ((size_t)(b * NH + h) * HW) * DD + d;
            *(float2*)(base + (size_t)pp * DD)       = r0;
            *(float2*)(base + (size_t)(pp + 8) * DD) = r1;
        }
    }
}

// ---------------------------------------------------------------------------
// Kernel 2: row logits. Block (y, bh). 16x16 threads, 6x6 tile, f32x2.
// ---------------------------------------------------------------------------
__global__ void __launch_bounds__(256) erow_kernel()
{
    extern __shared__ float sm[];
    float (*ts)[68] = (float(*)[68])sm;
    float (*fr)[68] = (float(*)[68])(sm + 96 * 68);

    const int y = blockIdx.x, bh = blockIdx.y, tid = threadIdx.x;

    const float* tb = d_t + (size_t)(bh * HH + y) * WW * DD;
    const float* fb = d_f + (size_t)(bh * HH + y) * WW * DD;
    for (int idx = tid; idx < 96 * 16; idx += 256) {
        int r = idx >> 4, dq = idx & 15;
        *(float4*)&ts[r][dq * 4] = *(const float4*)&tb[r * 64 + dq * 4];
        *(float4*)&fr[r][dq * 4] = *(const float4*)&fb[r * 64 + dq * 4];
    }
    __syncthreads();

    const int x0 = (tid >> 4) * 6;
    const int i0 = (tid & 15) * 6;

    u64 acc[6][6];
#pragma unroll
    for (int p = 0; p < 6; p++)
#pragma unroll
        for (int q = 0; q < 6; q++) acc[p][q] = 0ull;

#pragma unroll 4
    for (int ds = 0; ds < 16; ds++) {
        ulonglong2 av[6], bv[6];
#pragma unroll
        for (int p = 0; p < 6; p++) av[p] = *(const ulonglong2*)&ts[x0 + p][ds * 4];
#pragma unroll
        for (int q = 0; q < 6; q++) bv[q] = *(const ulonglong2*)&fr[i0 + q][ds * 4];
#pragma unroll
        for (int p = 0; p < 6; p++)
#pragma unroll
            for (int q = 0; q < 6; q++) {
                ffma2(acc[p][q], av[p].x, bv[q].x);
                ffma2(acc[p][q], av[p].y, bv[q].y);
            }
    }

    float* Eb = d_E + (size_t)(bh * HH + y) * WW * 192;
#pragma unroll
    for (int p = 0; p < 6; p++)
#pragma unroll
        for (int q = 0; q < 6; q++)
            Eb[(size_t)(x0 + p) * 192 + (i0 + q)] = lo2(acc[p][q]) + hi2(acc[p][q]);
}

// ---------------------------------------------------------------------------
// Kernel 3: column logits. Block (x, bh).
// ---------------------------------------------------------------------------
__global__ void __launch_bounds__(256) ecol_kernel()
{
    extern __shared__ float sm[];
    float (*tc)[68] = (float(*)[68])sm;
    float (*fc)[68] = (float(*)[68])(sm + 96 * 68);

    const int x = blockIdx.x, bh = blockIdx.y, tid = threadIdx.x;

    for (int idx = tid; idx < 96 * 16; idx += 256) {
        int r = idx >> 4, dq = idx & 15;
        size_t g = ((size_t)(bh * HH + r) * WW + x) * DD + dq * 4;
        *(float4*)&tc[r][dq * 4] = *(const float4*)&d_t[g];
        *(float4*)&fc[r][dq * 4] = *(const float4*)&d_f[g];
    }
    __syncthreads();

    const int y0 = (tid >> 4) * 6;
    const int i0 = (tid & 15) * 6;

    u64 acc[6][6];
#pragma unroll
    for (int p = 0; p < 6; p++)
#pragma unroll
        for (int q = 0; q < 6; q++) acc[p][q] = 0ull;

#pragma unroll 4
    for (int ds = 0; ds < 16; ds++) {
        ulonglong2 av[6], bv[6];
#pragma unroll
        for (int p = 0; p < 6; p++) av[p] = *(const ulonglong2*)&tc[y0 + p][ds * 4];
#pragma unroll
        for (int q = 0; q < 6; q++) bv[q] = *(const ulonglong2*)&fc[i0 + q][ds * 4];
#pragma unroll
        for (int p = 0; p < 6; p++)
#pragma unroll
            for (int q = 0; q < 6; q++) {
                ffma2(acc[p][q], av[p].x, bv[q].x);
                ffma2(acc[p][q], av[p].y, bv[q].y);
            }
    }

#pragma unroll
    for (int p = 0; p < 6; p++) {
        size_t base = ((size_t)(bh * HH + y0 + p) * WW + x) * 192 + 96;
#pragma unroll
        for (int q = 0; q < 6; q++) {
            float e = lo2(acc[p][q]) + hi2(acc[p][q]);
            if (i0 + q == y0 + p) e = -INFINITY;
            d_E[base + i0 + q] = e;
        }
    }
}

// Warp-per-row softmax over 192 logits held in Es[96][200].
__device__ __forceinline__ void softmax_rows(float (*Es)[200], int tid)
{
    const int w = tid >> 5, lane = tid & 31;
#pragma unroll 1
    for (int rr = 0; rr < 12; rr++) {
        const int r = w * 12 + rr;
        float m = -INFINITY;
#pragma unroll
        for (int k = 0; k < 6; k++) m = fmaxf(m, Es[r][lane + k * 32]);
#pragma unroll
        for (int off = 16; off; off >>= 1) m = fmaxf(m, __shfl_xor_sync(0xffffffffu, m, off));
        float s = 0.f;
        float ev[6];
#pragma unroll
        for (int k = 0; k < 6; k++) { ev[k] = __expf(Es[r][lane + k * 32] - m); s += ev[k]; }
#pragma unroll
        for (int off = 16; off; off >>= 1) s += __shfl_xor_sync(0xffffffffu, s, off);
        const float inv = 1.f / s;
#pragma unroll
        for (int k = 0; k < 6; k++) Es[r][lane + k * 32] = ev[k] * inv;
    }
}

// ---------------------------------------------------------------------------
// Kernel 4: column-attention output partial. Block (x, bh).
// ---------------------------------------------------------------------------
__global__ void __launch_bounds__(256) colout_kernel()
{
    extern __shared__ float sm[];
    float (*Es)[200] = (float(*)[200])sm;
    float (*gc)[68]  = (float(*)[68])(sm + 96 * 200);

    const int x = blockIdx.x, bh = blockIdx.y, tid = threadIdx.x;

    for (int idx = tid; idx < 96 * 48; idx += 256) {
        int r = idx / 48, jq = idx % 48;
        *(float4*)&Es[r][jq * 4] =
            *(const float4*)&d_E[((size_t)(bh * HH + r) * WW + x) * 192 + jq * 4];
    }
    for (int idx = tid; idx < 96 * 16; idx += 256) {
        int r = idx >> 4, dq = idx & 15;
        *(float4*)&gc[r][dq * 4] =
            *(const float4*)&d_g[((size_t)(bh * HH + r) * WW + x) * DD + dq * 4];
    }
    __syncthreads();

    softmax_rows(Es, tid);
    __syncthreads();

    for (int it = tid; it < 768; it += 256) {
        const int dq = it & 15;
        const int y0 = (it >> 4) * 2;
        float4 a0 = {0,0,0,0}, a1 = {0,0,0,0};
        for (int i = 0; i < 96; i += 4) {
            float4 w0 = *(const float4*)&Es[y0][96 + i];
            float4 w1 = *(const float4*)&Es[y0 + 1][96 + i];
            float4 g0 = *(const float4*)&gc[i][dq * 4];
            float4 g1 = *(const float4*)&gc[i + 1][dq * 4];
            float4 g2 = *(const float4*)&gc[i + 2][dq * 4];
            float4 g3 = *(const float4*)&gc[i + 3][dq * 4];
            a0.x += w0.x * g0.x + w0.y * g1.x + w0.z * g2.x + w0.w * g3.x;
            a0.y += w0.x * g0.y + w0.y * g1.y + w0.z * g2.y + w0.w * g3.y;
            a0.z += w0.x * g0.z + w0.y * g1.z + w0.z * g2.z + w0.w * g3.z;
            a0.w += w0.x * g0.w + w0.y * g1.w + w0.z * g2.w + w0.w * g3.w;
            a1.x += w1.x * g0.x + w1.y * g1.x + w1.z * g2.x + w1.w * g3.x;
            a1.y += w1.x * g0.y + w1.y * g1.y + w1.z * g2.y + w1.w * g3.y;
            a1.z += w1.x * g0.z + w1.y * g1.z + w1.z * g2.z + w1.w * g3.z;
            a1.w += w1.x * g0.w + w1.y * g1.w + w1.z * g2.w + w1.w * g3.w;
        }
        *(float4*)&d_O[((size_t)(bh * HH + y0) * WW + x) * DD + dq * 4]     = a0;
        *(float4*)&d_O[((size_t)(bh * HH + y0 + 1) * WW + x) * DD + dq * 4] = a1;
    }
}

// ---------------------------------------------------------------------------
// Kernel 5: row-attention output + combine + residual. Block (y, bh).
// ---------------------------------------------------------------------------
__global__ void __launch_bounds__(256) rowout_kernel(
    const float* __restrict__ v, const float* __restrict__ gamma,
    float* __restrict__ out)
{
    extern __shared__ float sm[];
    float (*Es)[200] = (float(*)[200])sm;
    float (*gr)[68]  = (float(*)[68])(sm + 96 * 200);

    const int y = blockIdx.x, bh = blockIdx.y, tid = threadIdx.x;

    const float* Eb = d_E + (size_t)(bh * HH + y) * WW * 192;
    for (int idx = tid; idx < 96 * 48; idx += 256) {
        int r = idx / 48, jq = idx % 48;
        *(float4*)&Es[r][jq * 4] = *(const float4*)&Eb[r * 192 + jq * 4];
    }
    const float* gb = d_g + (size_t)(bh * HH + y) * WW * DD;
    for (int idx = tid; idx < 96 * 16; idx += 256) {
        int r = idx >> 4, dq = idx & 15;
        *(float4*)&gr[r][dq * 4] = *(const float4*)&gb[r * 64 + dq * 4];
    }
    __syncthreads();

    softmax_rows(Es, tid);
    __syncthreads();

    const float gam = gamma[0];
    const int b = bh >> 3, h = bh & 7;
    const float* colp = d_O + (size_t)(bh * HH + y) * WW * DD;

    for (int it = tid; it < 768; it += 256) {
        const int xp = it % 48;
        const int dq = it / 48;
        const int x0 = xp * 2;
        float4 a0 = {0,0,0,0}, a1 = {0,0,0,0};
        for (int i = 0; i < 96; i += 4) {
            float4 w0 = *(const float4*)&Es[x0][i];
            float4 w1 = *(const float4*)&Es[x0 + 1][i];
            float4 g0 = *(const float4*)&gr[i][dq * 4];
            float4 g1 = *(const float4*)&gr[i + 1][dq * 4];
            float4 g2 = *(const float4*)&gr[i + 2][dq * 4];
            float4 g3 = *(const float4*)&gr[i + 3][dq * 4];
            a0.x += w0.x * g0.x + w0.y * g1.x + w0.z * g2.x + w0.w * g3.x;
            a0.y += w0.x * g0.y + w0.y * g1.y + w0.z * g2.y + w0.w * g3.y;
            a0.z += w0.x * g0.z + w0.y * g1.z + w0.z * g2.z + w0.w * g3.z;
            a0.w += w0.x * g0.w + w0.y * g1.w + w0.z * g2.w + w0.w * g3.w;
            a1.x += w1.x * g0.x + w1.y * g1.x + w1.z * g2.x + w1.w * g3.x;
            a1.y += w1.x * g0.y + w1.y * g1.y + w1.z * g2.y + w1.w * g3.y;
            a1.z += w1.x * g0.z + w1.y * g1.z + w1.z * g2.z + w1.w * g3.z;
            a1.w += w1.x * g0.w + w1.y * g1.w + w1.z * g2.w + w1.w * g3.w;
        }
        float4 cp0 = *(const float4*)&colp[(size_t)x0 * DD + dq * 4];
        float4 cp1 = *(const float4*)&colp[(size_t)(x0 + 1) * DD + dq * 4];
        const int c0 = h * 64 + dq * 4;
        size_t oa = (((size_t)(b * CC + c0)) * HH + y) * WW + x0;

        float2 s0, s1, s2, s3;
        s0.x = gam * (a0.x + cp0.x) + v[oa];
        s0.y = gam * (a1.x + cp1.x) + v[oa + 1];
        s1.x = gam * (a0.y + cp0.y) + v[oa + HW];
        s1.y = gam * (a1.y + cp1.y) + v[oa + HW + 1];
        s2.x = gam * (a0.z + cp0.z) + v[oa + 2 * HW];
        s2.y = gam * (a1.z + cp1.z) + v[oa + 2 * HW + 1];
        s3.x = gam * (a0.w + cp0.w) + v[oa + 3 * HW];
        s3.y = gam * (a1.w + cp1.w) + v[oa + 3 * HW + 1];
        *(float2*)&out[oa]          = s0;
        *(float2*)&out[oa + HW]     = s1;
        *(float2*)&out[oa + 2 * HW] = s2;
        *(float2*)&out[oa + 3 * HW] = s3;
    }
}

// ---------------------------------------------------------------------------
extern "C" void kernel_launch(void* const* d_in, const int* in_sizes, int n_in,
                              void* d_out, int out_size)
{
    const float* q     = (const float*)d_in[0];
    const float* v     = (const float*)d_in[1];
    const float* Wq    = (const float*)d_in[2];
    const float* bq    = (const float*)d_in[3];
    const float* Wk    = (const float*)d_in[4];
    const float* bk    = (const float*)d_in[5];
    const float* Wv    = (const float*)d_in[6];
    const float* bv    = (const float*)d_in[7];
    const float* gamma = (const float*)d_in[8];
    float* out = (float*)d_out;

    static __nv_bfloat16 *pAqh = nullptr, *pAql, *pAvh, *pAvl, *pWh, *pWl;
    if (!pAqh) {
        cudaGetSymbolAddress((void**)&pAqh, d_Aq_hi);
        cudaGetSymbolAddress((void**)&pAql, d_Aq_lo);
        cudaGetSymbolAddress((void**)&pAvh, d_Av_hi);
        cudaGetSymbolAddress((void**)&pAvl, d_Av_lo);
        cudaGetSymbolAddress((void**)&pWh,  d_Wh);
        cudaGetSymbolAddress((void**)&pWl,  d_Wl);
    }

    const int smE = 2 * 96 * 68 * 4;
    const int smO = (96 * 200 + 96 * 68) * 4;
    static bool attrs_set = false;
    if (!attrs_set) {
        cudaFuncSetAttribute(erow_kernel,   cudaFuncAttributeMaxDynamicSharedMemorySize, smE);
        cudaFuncSetAttribute(ecol_kernel,   cudaFuncAttributeMaxDynamicSharedMemorySize, smE);
        cudaFuncSetAttribute(colout_kernel, cudaFuncAttributeMaxDynamicSharedMemorySize, smO);
        cudaFuncSetAttribute(rowout_kernel, cudaFuncAttributeMaxDynamicSharedMemorySize, smO);
        attrs_set = true;
    }

    // Prepasses: split inputs (transpose) + weights
    dim3 spGrid(HW / 32, CC / 32, BB);
    splitX_kernel<<<spGrid, 256>>>(q, pAqh, pAql);
    splitX_kernel<<<spGrid, 256>>>(v, pAvh, pAvl);
    splitW_kernel<<<(CC * CC + 255) / 256, 256>>>(Wq, pWh, pWl);
    splitW_kernel<<<(CC * CC + 255) / 256, 256>>>(Wk, pWh + CC * CC, pWl + CC * CC);
    splitW_kernel<<<(CC * CC + 255) / 256, 256>>>(Wv, pWh + 2 * CC * CC, pWl + 2 * CC * CC);

    // Conv GEMMs on tensor cores (mma.sync)
    dim3 cg(MTOT / 128, CC / 128);   // 288 x 4
    conv_wmma_kernel<<<cg, 256>>>(pAqh, pAql, pWh,              pWl,              bq, SCALING, 0);
    conv_wmma_kernel<<<cg, 256>>>(pAqh, pAql, pWh + CC * CC,     pWl + CC * CC,     bk, 1.0f,    1);
    conv_wmma_kernel<<<cg, 256>>>(pAvh, pAvl, pWh + 2 * CC * CC, pWl + 2 * CC * CC, bv, 1.0f,    2);

    // Attention
    dim3 attnGrid(96, BHD);
    erow_kernel<<<attnGrid, 256, smE>>>();
    ecol_kernel<<<attnGrid, 256, smE>>>();
    colout_kernel<<<attnGrid, 256, smO>>>();
    rowout_kernel<<<attnGrid, 256, smO>>>(v, gamma, out);
}

// round 5
// speedup vs baseline: 3.2175x; 1.1401x over previous
#include <cuda_runtime.h>
#include <cuda_bf16.h>
#include <math.h>
#include <cstdint>

#define BB 4
#define NH 8
#define BHD 32
#define HH 96
#define WW 96
#define CC 512
#define DD 64
#define HW 9216
#define MTOT (BB * HW)      // 36864
#define SCALING 0.125f

typedef unsigned long long u64;

// ---------------------------------------------------------------------------
// Device-global scratch
// ---------------------------------------------------------------------------
__device__ float d_t[(size_t)BHD * HW * DD];
__device__ float d_f[(size_t)BHD * HW * DD];
__device__ float d_g[(size_t)BHD * HW * DD];
__device__ float d_Er[(size_t)BHD * HW * 96];            // row logits (fp32)
__device__ __nv_bfloat16 d_Ar[(size_t)BHD * HW * 96];    // row probs (bf16)
__device__ float d_O[(size_t)BHD * HW * DD];             // column partial
// bf16 hi/lo split operands, K-major [m][c]
__device__ __nv_bfloat16 d_Aq_hi[(size_t)MTOT * CC];
__device__ __nv_bfloat16 d_Aq_lo[(size_t)MTOT * CC];
__device__ __nv_bfloat16 d_Av_hi[(size_t)MTOT * CC];
__device__ __nv_bfloat16 d_Av_lo[(size_t)MTOT * CC];
__device__ __nv_bfloat16 d_Wh[3 * CC * CC];
__device__ __nv_bfloat16 d_Wl[3 * CC * CC];

// ---------------------------------------------------------------------------
// Helpers (generic PTX: sm_80+ features only)
// ---------------------------------------------------------------------------
__device__ __forceinline__ uint32_t smem_u32(const void* p) {
    uint32_t a;
    asm("{ .reg .u64 t; cvta.to.shared.u64 t, %1; cvt.u32.u64 %0, t; }" : "=r"(a) : "l"(p));
    return a;
}
__device__ __forceinline__ void cpa16(uint32_t d, const void* s) {
    asm volatile("cp.async.ca.shared.global [%0], [%1], 16;" :: "r"(d), "l"(s));
}
__device__ __forceinline__ void ldmx4(uint32_t* r, uint32_t addr) {
    asm volatile("ldmatrix.sync.aligned.m8n8.x4.shared.b16 {%0,%1,%2,%3}, [%4];"
        : "=r"(r[0]), "=r"(r[1]), "=r"(r[2]), "=r"(r[3]) : "r"(addr));
}
__device__ __forceinline__ void mma16816(float* c, const uint32_t* a,
                                         uint32_t b0, uint32_t b1) {
    asm volatile(
        "mma.sync.aligned.m16n8k16.row.col.f32.bf16.bf16.f32 "
        "{%0,%1,%2,%3}, {%4,%5,%6,%7}, {%8,%9}, {%0,%1,%2,%3};"
        : "+f"(c[0]), "+f"(c[1]), "+f"(c[2]), "+f"(c[3])
        : "r"(a[0]), "r"(a[1]), "r"(a[2]), "r"(a[3]), "r"(b0), "r"(b1));
}

// ---- packed f32x2 helpers ---------------------------------------------------
__device__ __forceinline__ void ffma2(u64& d, u64 a, u64 b) {
    asm("fma.rn.f32x2 %0, %1, %2, %0;" : "+l"(d) : "l"(a), "l"(b));
}
__device__ __forceinline__ float lo2(u64 v) { return __uint_as_float((unsigned)v); }
__device__ __forceinline__ float hi2(u64 v) { return __uint_as_float((unsigned)(v >> 32)); }

// ---------------------------------------------------------------------------
// Prepass A: transpose + bf16 split  X[b][c][px] -> A_hi/A_lo [m][c]
// ---------------------------------------------------------------------------
__global__ void __launch_bounds__(256) splitX_kernel(
    const float* __restrict__ X, __nv_bfloat16* __restrict__ hi,
    __nv_bfloat16* __restrict__ lo)
{
    __shared__ float tile[32][33];
    const int t   = threadIdx.x;
    const int px0 = blockIdx.x * 32;
    const int c0  = blockIdx.y * 32;
    const int b   = blockIdx.z;

#pragma unroll
    for (int r = 0; r < 4; r++) {
        int ci = (t >> 5) + r * 8, pj = t & 31;
        tile[ci][pj] = X[((size_t)b * CC + c0 + ci) * HW + px0 + pj];
    }
    __syncthreads();
#pragma unroll
    for (int r = 0; r < 4; r++) {
        int pj = (t >> 5) + r * 8, ci = t & 31;
        float v = tile[ci][pj];
        __nv_bfloat16 h = __float2bfloat16(v);
        float rem = v - __bfloat162float(h);
        size_t idx = ((size_t)b * HW + px0 + pj) * CC + c0 + ci;
        hi[idx] = h;
        lo[idx] = __float2bfloat16(rem);
    }
}

__global__ void __launch_bounds__(256) splitW_kernel(
    const float* __restrict__ W, __nv_bfloat16* __restrict__ hi,
    __nv_bfloat16* __restrict__ lo)
{
    int i = blockIdx.x * 256 + threadIdx.x;
    if (i < CC * CC) {
        float v = W[i];
        __nv_bfloat16 h = __float2bfloat16(v);
        hi[i] = h;
        lo[i] = __float2bfloat16(v - __bfloat162float(h));
    }
}

// ---------------------------------------------------------------------------
// Conv GEMM on mma.sync, cp.async 2-stage pipeline.
// Block tile 128x128, K chunk 32, 8 warps (warp tile 32x64), KPAD=40.
// ---------------------------------------------------------------------------
#define KPAD 40
#define STGB (4 * 128 * KPAD * 2)   // bytes per stage (A hi,lo + B hi,lo)
#define AHI 0
#define ALO (128 * KPAD * 2)
#define BHI (2 * 128 * KPAD * 2)
#define BLO (3 * 128 * KPAD * 2)

__global__ void __launch_bounds__(256) conv_wmma_kernel(
    const __nv_bfloat16* __restrict__ Ah, const __nv_bfloat16* __restrict__ Al,
    const __nv_bfloat16* __restrict__ Bh, const __nv_bfloat16* __restrict__ Bl,
    const float* __restrict__ bias, float scale, int sel)
{
    extern __shared__ __align__(16) __nv_bfloat16 cs[];
    const uint32_t sb = smem_u32(cs);

    float* dst = (sel == 0) ? d_t : (sel == 1) ? d_f : d_g;

    const int tid  = threadIdx.x;
    const int lane = tid & 31;
    const int warp = tid >> 5;
    const int wm   = warp & 3;
    const int wn   = warp >> 2;

    const int M0 = blockIdx.x * 128;
    const int o0 = blockIdx.y * 128;

    // copy mapping: crow 0..63 (+64 on second pass), cq selects 8-col segment
    const int crow = tid >> 2, cq = tid & 3;
    const __nv_bfloat16* pAh = Ah + (size_t)(M0 + crow) * CC + cq * 8;
    const __nv_bfloat16* pAl = Al + (size_t)(M0 + crow) * CC + cq * 8;
    const __nv_bfloat16* pBh = Bh + (size_t)(o0 + crow) * CC + cq * 8;
    const __nv_bfloat16* pBl = Bl + (size_t)(o0 + crow) * CC + cq * 8;

    float acc[2][8][4];
#pragma unroll
    for (int mi = 0; mi < 2; mi++)
#pragma unroll
        for (int nf = 0; nf < 8; nf++)
#pragma unroll
            for (int k = 0; k < 4; k++) acc[mi][nf][k] = 0.f;

    const int lrow = lane & 15;
    const int lcol = (lane >> 4) * 8;

    // prologue: stage chunk 0 into buffer 0
    {
#pragma unroll
        for (int r = 0; r < 2; r++) {
            const size_t go = (size_t)r * 64 * CC;
            uint32_t so = sb + ((crow + r * 64) * KPAD + cq * 8) * 2;
            cpa16(so + AHI, pAh + go);
            cpa16(so + ALO, pAl + go);
            cpa16(so + BHI, pBh + go);
            cpa16(so + BLO, pBl + go);
        }
        asm volatile("cp.async.commit_group;");
    }

    for (int ch = 0; ch < 16; ch++) {
        const int s = ch & 1;
        if (ch + 1 < 16) {
            const int k1 = (ch + 1) * 32;
            const uint32_t stb = sb + ((ch + 1) & 1) * STGB;
#pragma unroll
            for (int r = 0; r < 2; r++) {
                const size_t go = (size_t)r * 64 * CC + k1;
                uint32_t so = stb + ((crow + r * 64) * KPAD + cq * 8) * 2;
                cpa16(so + AHI, pAh + go);
                cpa16(so + ALO, pAl + go);
                cpa16(so + BHI, pBh + go);
                cpa16(so + BLO, pBl + go);
            }
            asm volatile("cp.async.commit_group;");
            asm volatile("cp.async.wait_group 1;");
        } else {
            asm volatile("cp.async.wait_group 0;");
        }
        __syncthreads();

        const uint32_t stb = sb + s * STGB;
#pragma unroll
        for (int ks = 0; ks < 2; ks++) {
            const int kc = ks * 16 + lcol;

            uint32_t a[2][2][4];
#pragma unroll
            for (int sp = 0; sp < 2; sp++)
#pragma unroll
                for (int mi = 0; mi < 2; mi++) {
                    uint32_t off = stb + (sp ? ALO : AHI) +
                                   ((wm * 32 + mi * 16 + lrow) * KPAD + kc) * 2;
                    ldmx4(a[sp][mi], off);
                }

#pragma unroll
            for (int np = 0; np < 4; np++) {
                uint32_t bh[4], bl[4];
                uint32_t offh = stb + BHI + ((wn * 64 + np * 16 + lrow) * KPAD + kc) * 2;
                uint32_t offl = stb + BLO + ((wn * 64 + np * 16 + lrow) * KPAD + kc) * 2;
                ldmx4(bh, offh);
                ldmx4(bl, offl);
#pragma unroll
                for (int mi = 0; mi < 2; mi++)
#pragma unroll
                    for (int hf = 0; hf < 2; hf++) {
                        const int nf = np * 2 + hf;
                        mma16816(acc[mi][nf], a[0][mi], bh[hf], bh[2 + hf]);
                        mma16816(acc[mi][nf], a[0][mi], bl[hf], bl[2 + hf]);
                        mma16816(acc[mi][nf], a[1][mi], bh[hf], bh[2 + hf]);
                    }
            }
        }
        __syncthreads();
    }

    // epilogue: bias + scale, write permuted [bh][pp][d]
#pragma unroll
    for (int mi = 0; mi < 2; mi++) {
        const int m  = M0 + wm * 32 + mi * 16 + (lane >> 2);
        const int b  = m / HW;
        const int pp = m % HW;
#pragma unroll
        for (int nf = 0; nf < 8; nf++) {
            const int o = o0 + wn * 64 + nf * 8 + (lane & 3) * 2;
            const int h = o >> 6, d = o & 63;
            const float b0 = bias[o], b1 = bias[o + 1];
            float2 r0, r1;
            r0.x = (acc[mi][nf][0] + b0) * scale;
            r0.y = (acc[mi][nf][1] + b1) * scale;
            r1.x = (acc[mi][nf][2] + b0) * scale;
            r1.y = (acc[mi][nf][3] + b1) * scale;
            float* base = dst + ((size_t)(b * NH + h) * HW) * DD + d;
            *(float2*)(base + (size_t)pp * DD)       = r0;
            *(float2*)(base + (size_t)(pp + 8) * DD) = r1;
        }
    }
}

// ---------------------------------------------------------------------------
// Kernel 2: row logits -> d_Er. Block (y, bh). 6x6 f32x2 tiles.
// ---------------------------------------------------------------------------
__global__ void __launch_bounds__(256) erow_kernel()
{
    extern __shared__ float sm[];
    float (*ts)[68] = (float(*)[68])sm;
    float (*fr)[68] = (float(*)[68])(sm + 96 * 68);

    const int y = blockIdx.x, bh = blockIdx.y, tid = threadIdx.x;

    const float* tb = d_t + (size_t)(bh * HH + y) * WW * DD;
    const float* fb = d_f + (size_t)(bh * HH + y) * WW * DD;
    for (int idx = tid; idx < 96 * 16; idx += 256) {
        int r = idx >> 4, dq = idx & 15;
        *(float4*)&ts[r][dq * 4] = *(const float4*)&tb[r * 64 + dq * 4];
        *(float4*)&fr[r][dq * 4] = *(const float4*)&fb[r * 64 + dq * 4];
    }
    __syncthreads();

    const int x0 = (tid >> 4) * 6;
    const int i0 = (tid & 15) * 6;

    u64 acc[6][6];
#pragma unroll
    for (int p = 0; p < 6; p++)
#pragma unroll
        for (int q = 0; q < 6; q++) acc[p][q] = 0ull;

#pragma unroll 4
    for (int ds = 0; ds < 16; ds++) {
        ulonglong2 av[6], bv[6];
#pragma unroll
        for (int p = 0; p < 6; p++) av[p] = *(const ulonglong2*)&ts[x0 + p][ds * 4];
#pragma unroll
        for (int q = 0; q < 6; q++) bv[q] = *(const ulonglong2*)&fr[i0 + q][ds * 4];
#pragma unroll
        for (int p = 0; p < 6; p++)
#pragma unroll
            for (int q = 0; q < 6; q++) {
                ffma2(acc[p][q], av[p].x, bv[q].x);
                ffma2(acc[p][q], av[p].y, bv[q].y);
            }
    }

    float* Eb = d_Er + (size_t)(bh * HH + y) * WW * 96;
#pragma unroll
    for (int p = 0; p < 6; p++)
#pragma unroll
        for (int q = 0; q < 6; q++)
            Eb[(size_t)(x0 + p) * 96 + (i0 + q)] = lo2(acc[p][q]) + hi2(acc[p][q]);
}

// ---------------------------------------------------------------------------
// Kernel 3 (fused): per (x, bh):
//   e_col in SMEM (never hits DRAM), softmax over 192 (reads d_Er slice),
//   emit a_row (bf16) to d_Ar, compute column output partial -> d_O.
// SMEM: tc[96][68], fg[96][68] (f then g), Ec[96][100], Er[96][100] = 129 KB
// ---------------------------------------------------------------------------
__global__ void __launch_bounds__(256) fusedcol_kernel()
{
    extern __shared__ float sm[];
    float (*tc)[68]  = (float(*)[68])sm;
    float (*fg)[68]  = (float(*)[68])(sm + 96 * 68);
    float (*Ec)[100] = (float(*)[100])(sm + 2 * 96 * 68);
    float (*Er)[100] = (float(*)[100])(sm + 2 * 96 * 68 + 96 * 100);

    const int x = blockIdx.x, bh = blockIdx.y, tid = threadIdx.x;

    // load t,f columns
    for (int idx = tid; idx < 96 * 16; idx += 256) {
        int r = idx >> 4, dq = idx & 15;
        size_t g = ((size_t)(bh * HH + r) * WW + x) * DD + dq * 4;
        *(float4*)&tc[r][dq * 4] = *(const float4*)&d_t[g];
        *(float4*)&fg[r][dq * 4] = *(const float4*)&d_f[g];
    }
    // load row-logit slice
    for (int idx = tid; idx < 96 * 24; idx += 256) {
        int r = idx / 24, c4 = idx % 24;
        *(float4*)&Er[r][c4 * 4] =
            *(const float4*)&d_Er[((size_t)(bh * HH + r) * WW + x) * 96 + c4 * 4];
    }
    __syncthreads();

    // column logits into SMEM (6x6 f32x2 tiles) with diag mask
    {
        const int y0 = (tid >> 4) * 6;
        const int i0 = (tid & 15) * 6;
        u64 acc[6][6];
#pragma unroll
        for (int p = 0; p < 6; p++)
#pragma unroll
            for (int q = 0; q < 6; q++) acc[p][q] = 0ull;

#pragma unroll 4
        for (int ds = 0; ds < 16; ds++) {
            ulonglong2 av[6], bv[6];
#pragma unroll
            for (int p = 0; p < 6; p++) av[p] = *(const ulonglong2*)&tc[y0 + p][ds * 4];
#pragma unroll
            for (int q = 0; q < 6; q++) bv[q] = *(const ulonglong2*)&fg[i0 + q][ds * 4];
#pragma unroll
            for (int p = 0; p < 6; p++)
#pragma unroll
                for (int q = 0; q < 6; q++) {
                    ffma2(acc[p][q], av[p].x, bv[q].x);
                    ffma2(acc[p][q], av[p].y, bv[q].y);
                }
        }
#pragma unroll
        for (int p = 0; p < 6; p++)
#pragma unroll
            for (int q = 0; q < 6; q++) {
                float e = lo2(acc[p][q]) + hi2(acc[p][q]);
                if (i0 + q == y0 + p) e = -INFINITY;
                Ec[y0 + p][i0 + q] = e;
            }
    }
    __syncthreads();   // f done, Ec complete

    // load g columns into fg (overwrites f)
    for (int idx = tid; idx < 96 * 16; idx += 256) {
        int r = idx >> 4, dq = idx & 15;
        *(float4*)&fg[r][dq * 4] =
            *(const float4*)&d_g[((size_t)(bh * HH + r) * WW + x) * DD + dq * 4];
    }

    // softmax over concat(Er[r][0..95], Ec[r][0..95]); warp per row
    {
        const int w = tid >> 5, lane = tid & 31;
#pragma unroll 1
        for (int rr = 0; rr < 12; rr++) {
            const int r = w * 12 + rr;
            float vr[3], vc[3];
#pragma unroll
            for (int k = 0; k < 3; k++) { vr[k] = Er[r][lane + k * 32]; vc[k] = Ec[r][lane + k * 32]; }
            float m = -INFINITY;
#pragma unroll
            for (int k = 0; k < 3; k++) m = fmaxf(m, fmaxf(vr[k], vc[k]));
#pragma unroll
            for (int off = 16; off; off >>= 1) m = fmaxf(m, __shfl_xor_sync(0xffffffffu, m, off));
            float s = 0.f;
#pragma unroll
            for (int k = 0; k < 3; k++) {
                vr[k] = __expf(vr[k] - m); vc[k] = __expf(vc[k] - m);
                s += vr[k] + vc[k];
            }
#pragma unroll
            for (int off = 16; off; off >>= 1) s += __shfl_xor_sync(0xffffffffu, s, off);
            const float inv = 1.f / s;
#pragma unroll
            for (int k = 0; k < 3; k++) {
                Er[r][lane + k * 32] = vr[k] * inv;
                Ec[r][lane + k * 32] = vc[k] * inv;
            }
        }
    }
    __syncthreads();

    // emit a_row probs as bf16
    for (int idx = tid; idx < 96 * 48; idx += 256) {
        int yv = idx / 48, i2 = idx % 48;
        float2 pr = { Er[yv][i2 * 2], Er[yv][i2 * 2 + 1] };
        *(__nv_bfloat162*)&d_Ar[((size_t)(bh * HH + yv) * WW + x) * 96 + i2 * 2] =
            __float22bfloat162_rn(pr);
    }

    // column output partial
    for (int it = tid; it < 768; it += 256) {
        const int dq = it & 15;
        const int y0 = (it >> 4) * 2;
        float4 a0 = {0,0,0,0}, a1 = {0,0,0,0};
        for (int i = 0; i < 96; i += 4) {
            float4 w0 = *(const float4*)&Ec[y0][i];
            float4 w1 = *(const float4*)&Ec[y0 + 1][i];
            float4 g0 = *(const float4*)&fg[i][dq * 4];
            float4 g1 = *(const float4*)&fg[i + 1][dq * 4];
            float4 g2 = *(const float4*)&fg[i + 2][dq * 4];
            float4 g3 = *(const float4*)&fg[i + 3][dq * 4];
            a0.x += w0.x * g0.x + w0.y * g1.x + w0.z * g2.x + w0.w * g3.x;
            a0.y += w0.x * g0.y + w0.y * g1.y + w0.z * g2.y + w0.w * g3.y;
            a0.z += w0.x * g0.z + w0.y * g1.z + w0.z * g2.z + w0.w * g3.z;
            a0.w += w0.x * g0.w + w0.y * g1.w + w0.z * g2.w + w0.w * g3.w;
            a1.x += w1.x * g0.x + w1.y * g1.x + w1.z * g2.x + w1.w * g3.x;
            a1.y += w1.x * g0.y + w1.y * g1.y + w1.z * g2.y + w1.w * g3.y;
            a1.z += w1.x * g0.z + w1.y * g1.z + w1.z * g2.z + w1.w * g3.z;
            a1.w += w1.x * g0.w + w1.y * g1.w + w1.z * g2.w + w1.w * g3.w;
        }
        *(float4*)&d_O[((size_t)(bh * HH + y0) * WW + x) * DD + dq * 4]     = a0;
        *(float4*)&d_O[((size_t)(bh * HH + y0 + 1) * WW + x) * DD + dq * 4] = a1;
    }
}

// ---------------------------------------------------------------------------
// Kernel 4: row output from bf16 probs + combine + residual. Block (y, bh).
// ---------------------------------------------------------------------------
__global__ void __launch_bounds__(256) rowout_kernel(
    const float* __restrict__ v, const float* __restrict__ gamma,
    float* __restrict__ out)
{
    extern __shared__ char smc[];
    __nv_bfloat16 (*Ab)[104] = (__nv_bfloat16(*)[104])smc;          // 19968 B
    float (*gr)[68] = (float(*)[68])(smc + 96 * 104 * 2);           // 26112 B

    const int y = blockIdx.x, bh = blockIdx.y, tid = threadIdx.x;

    const __nv_bfloat16* ab = d_Ar + (size_t)(bh * HH + y) * WW * 96;
    for (int idx = tid; idx < 96 * 12; idx += 256) {
        int r = idx / 12, c8 = idx % 12;
        *(uint4*)&Ab[r][c8 * 8] = *(const uint4*)&ab[r * 96 + c8 * 8];
    }
    const float* gb = d_g + (size_t)(bh * HH + y) * WW * DD;
    for (int idx = tid; idx < 96 * 16; idx += 256) {
        int r = idx >> 4, dq = idx & 15;
        *(float4*)&gr[r][dq * 4] = *(const float4*)&gb[r * 64 + dq * 4];
    }
    __syncthreads();

    const float gam = gamma[0];
    const int b = bh >> 3, h = bh & 7;
    const float* colp = d_O + (size_t)(bh * HH + y) * WW * DD;

    for (int it = tid; it < 768; it += 256) {
        const int xp = it % 48;
        const int dq = it / 48;
        const int x0 = xp * 2;
        float4 a0 = {0,0,0,0}, a1 = {0,0,0,0};
        for (int i = 0; i < 96; i += 4) {
            float2 p00 = __bfloat1622float2(*(const __nv_bfloat162*)&Ab[x0][i]);
            float2 p01 = __bfloat1622float2(*(const __nv_bfloat162*)&Ab[x0][i + 2]);
            float2 p10 = __bfloat1622float2(*(const __nv_bfloat162*)&Ab[x0 + 1][i]);
            float2 p11 = __bfloat1622float2(*(const __nv_bfloat162*)&Ab[x0 + 1][i + 2]);
            float4 w0 = { p00.x, p00.y, p01.x, p01.y };
            float4 w1 = { p10.x, p10.y, p11.x, p11.y };
            float4 g0 = *(const float4*)&gr[i][dq * 4];
            float4 g1 = *(const float4*)&gr[i + 1][dq * 4];
            float4 g2 = *(const float4*)&gr[i + 2][dq * 4];
            float4 g3 = *(const float4*)&gr[i + 3][dq * 4];
            a0.x += w0.x * g0.x + w0.y * g1.x + w0.z * g2.x + w0.w * g3.x;
            a0.y += w0.x * g0.y + w0.y * g1.y + w0.z * g2.y + w0.w * g3.y;
            a0.z += w0.x * g0.z + w0.y * g1.z + w0.z * g2.z + w0.w * g3.z;
            a0.w += w0.x * g0.w + w0.y * g1.w + w0.z * g2.w + w0.w * g3.w;
            a1.x += w1.x * g0.x + w1.y * g1.x + w1.z * g2.x + w1.w * g3.x;
            a1.y += w1.x * g0.y + w1.y * g1.y + w1.z * g2.y + w1.w * g3.y;
            a1.z += w1.x * g0.z + w1.y * g1.z + w1.z * g2.z + w1.w * g3.z;
            a1.w += w1.x * g0.w + w1.y * g1.w + w1.z * g2.w + w1.w * g3.w;
        }
        float4 cp0 = *(const float4*)&colp[(size_t)x0 * DD + dq * 4];
        float4 cp1 = *(const float4*)&colp[(size_t)(x0 + 1) * DD + dq * 4];
        const int c0 = h * 64 + dq * 4;
        size_t oa = (((size_t)(b * CC + c0)) * HH + y) * WW + x0;

        float2 s0, s1, s2, s3;
        s0.x = gam * (a0.x + cp0.x) + v[oa];
        s0.y = gam * (a1.x + cp1.x) + v[oa + 1];
        s1.x = gam * (a0.y + cp0.y) + v[oa + HW];
        s1.y = gam * (a1.y + cp1.y) + v[oa + HW + 1];
        s2.x = gam * (a0.z + cp0.z) + v[oa + 2 * HW];
        s2.y = gam * (a1.z + cp1.z) + v[oa + 2 * HW + 1];
        s3.x = gam * (a0.w + cp0.w) + v[oa + 3 * HW];
        s3.y = gam * (a1.w + cp1.w) + v[oa + 3 * HW + 1];
        *(float2*)&out[oa]          = s0;
        *(float2*)&out[oa + HW]     = s1;
        *(float2*)&out[oa + 2 * HW] = s2;
        *(float2*)&out[oa + 3 * HW] = s3;
    }
}

// ---------------------------------------------------------------------------
extern "C" void kernel_launch(void* const* d_in, const int* in_sizes, int n_in,
                              void* d_out, int out_size)
{
    const float* q     = (const float*)d_in[0];
    const float* v     = (const float*)d_in[1];
    const float* Wq    = (const float*)d_in[2];
    const float* bq    = (const float*)d_in[3];
    const float* Wk    = (const float*)d_in[4];
    const float* bk    = (const float*)d_in[5];
    const float* Wv    = (const float*)d_in[6];
    const float* bv    = (const float*)d_in[7];
    const float* gamma = (const float*)d_in[8];
    float* out = (float*)d_out;

    static __nv_bfloat16 *pAqh = nullptr, *pAql, *pAvh, *pAvl, *pWh, *pWl;
    if (!pAqh) {
        cudaGetSymbolAddress((void**)&pAqh, d_Aq_hi);
        cudaGetSymbolAddress((void**)&pAql, d_Aq_lo);
        cudaGetSymbolAddress((void**)&pAvh, d_Av_hi);
        cudaGetSymbolAddress((void**)&pAvl, d_Av_lo);
        cudaGetSymbolAddress((void**)&pWh,  d_Wh);
        cudaGetSymbolAddress((void**)&pWl,  d_Wl);
    }

    const int smConv = 2 * STGB;                        // 81920
    const int smE    = 2 * 96 * 68 * 4;                 // 52224
    const int smF    = (2 * 96 * 68 + 2 * 96 * 100) * 4; // 129024
    const int smR    = 96 * 104 * 2 + 96 * 68 * 4;      // 46080
    static bool attrs_set = false;
    if (!attrs_set) {
        cudaFuncSetAttribute(conv_wmma_kernel, cudaFuncAttributeMaxDynamicSharedMemorySize, smConv);
        cudaFuncSetAttribute(erow_kernel,     cudaFuncAttributeMaxDynamicSharedMemorySize, smE);
        cudaFuncSetAttribute(fusedcol_kernel, cudaFuncAttributeMaxDynamicSharedMemorySize, smF);
        cudaFuncSetAttribute(rowout_kernel,   cudaFuncAttributeMaxDynamicSharedMemorySize, smR);
        attrs_set = true;
    }

    // Prepasses
    dim3 spGrid(HW / 32, CC / 32, BB);
    splitX_kernel<<<spGrid, 256>>>(q, pAqh, pAql);
    splitX_kernel<<<spGrid, 256>>>(v, pAvh, pAvl);
    splitW_kernel<<<(CC * CC + 255) / 256, 256>>>(Wq, pWh, pWl);
    splitW_kernel<<<(CC * CC + 255) / 256, 256>>>(Wk, pWh + CC * CC, pWl + CC * CC);
    splitW_kernel<<<(CC * CC + 255) / 256, 256>>>(Wv, pWh + 2 * CC * CC, pWl + 2 * CC * CC);

    // Conv GEMMs (mma.sync + cp.async pipeline)
    dim3 cg(MTOT / 128, CC / 128);   // 288 x 4
    conv_wmma_kernel<<<cg, 256, smConv>>>(pAqh, pAql, pWh,              pWl,              bq, SCALING, 0);
    conv_wmma_kernel<<<cg, 256, smConv>>>(pAqh, pAql, pWh + CC * CC,     pWl + CC * CC,     bk, 1.0f,    1);
    conv_wmma_kernel<<<cg, 256, smConv>>>(pAvh, pAvl, pWh + 2 * CC * CC, pWl + 2 * CC * CC, bv, 1.0f,    2);

    // Attention
    dim3 attnGrid(96, BHD);
    erow_kernel<<<attnGrid, 256, smE>>>();
    fusedcol_kernel<<<attnGrid, 256, smF>>>();
    rowout_kernel<<<attnGrid, 256, smR>>>(v, gamma, out);
}

// round 6
// speedup vs baseline: 5.3625x; 1.6666x over previous
#include <cuda_runtime.h>
#include <cuda_bf16.h>
#include <math.h>
#include <cstdint>

#define BB 4
#define NH 8
#define BHD 32
#define HH 96
#define WW 96
#define CC 512
#define DD 64
#define HW 9216
#define MTOT (BB * HW)      // 36864
#define SCALING 0.125f

typedef unsigned long long u64;
typedef __nv_bfloat16 bf16;
typedef __nv_bfloat162 bf162;

// ---------------------------------------------------------------------------
// Device-global scratch
// ---------------------------------------------------------------------------
__device__ float d_Er[(size_t)BHD * HW * 96];   // row logits (fp32)
__device__ bf16  d_Ar[(size_t)BHD * HW * 96];   // row probs (bf16)
__device__ float d_O [(size_t)BHD * HW * DD];   // column partial (fp32)
// conv outputs (attention operands)
__device__ bf16 d_tbh[(size_t)BHD * HW * DD];
__device__ bf16 d_tbl[(size_t)BHD * HW * DD];
__device__ bf16 d_fbh[(size_t)BHD * HW * DD];
__device__ bf16 d_fbl[(size_t)BHD * HW * DD];
__device__ bf16 d_gb [(size_t)BHD * HW * DD];
// bf16 hi/lo split GEMM inputs, K-major [m][c]
__device__ bf16 d_Aq_hi[(size_t)MTOT * CC];
__device__ bf16 d_Aq_lo[(size_t)MTOT * CC];
__device__ bf16 d_Av_hi[(size_t)MTOT * CC];
__device__ bf16 d_Av_lo[(size_t)MTOT * CC];
__device__ bf16 d_Wh[3 * CC * CC];
__device__ bf16 d_Wl[3 * CC * CC];

// ---------------------------------------------------------------------------
// Helpers (generic PTX: sm_80+ features only)
// ---------------------------------------------------------------------------
__device__ __forceinline__ uint32_t smem_u32(const void* p) {
    uint32_t a;
    asm("{ .reg .u64 t; cvta.to.shared.u64 t, %1; cvt.u32.u64 %0, t; }" : "=r"(a) : "l"(p));
    return a;
}
__device__ __forceinline__ void cpa16(uint32_t d, const void* s) {
    asm volatile("cp.async.ca.shared.global [%0], [%1], 16;" :: "r"(d), "l"(s));
}
__device__ __forceinline__ void ldmx4(uint32_t* r, uint32_t addr) {
    asm volatile("ldmatrix.sync.aligned.m8n8.x4.shared.b16 {%0,%1,%2,%3}, [%4];"
        : "=r"(r[0]), "=r"(r[1]), "=r"(r[2]), "=r"(r[3]) : "r"(addr));
}
__device__ __forceinline__ void ldmxt4(uint32_t* r, uint32_t addr) {
    asm volatile("ldmatrix.sync.aligned.m8n8.x4.trans.shared.b16 {%0,%1,%2,%3}, [%4];"
        : "=r"(r[0]), "=r"(r[1]), "=r"(r[2]), "=r"(r[3]) : "r"(addr));
}
__device__ __forceinline__ void ldmx2(uint32_t* r, uint32_t addr) {
    asm volatile("ldmatrix.sync.aligned.m8n8.x2.shared.b16 {%0,%1}, [%2];"
        : "=r"(r[0]), "=r"(r[1]) : "r"(addr));
}
__device__ __forceinline__ void mma16816(float* c, const uint32_t* a,
                                         uint32_t b0, uint32_t b1) {
    asm volatile(
        "mma.sync.aligned.m16n8k16.row.col.f32.bf16.bf16.f32 "
        "{%0,%1,%2,%3}, {%4,%5,%6,%7}, {%8,%9}, {%0,%1,%2,%3};"
        : "+f"(c[0]), "+f"(c[1]), "+f"(c[2]), "+f"(c[3])
        : "r"(a[0]), "r"(a[1]), "r"(a[2]), "r"(a[3]), "r"(b0), "r"(b1));
}

// ---------------------------------------------------------------------------
// Prepass A: transpose + bf16 split  X[b][c][px] -> A_hi/A_lo [m][c]
// ---------------------------------------------------------------------------
__global__ void __launch_bounds__(256) splitX_kernel(
    const float* __restrict__ X, bf16* __restrict__ hi, bf16* __restrict__ lo)
{
    __shared__ float tile[32][33];
    const int t   = threadIdx.x;
    const int px0 = blockIdx.x * 32;
    const int c0  = blockIdx.y * 32;
    const int b   = blockIdx.z;

#pragma unroll
    for (int r = 0; r < 4; r++) {
        int ci = (t >> 5) + r * 8, pj = t & 31;
        tile[ci][pj] = X[((size_t)b * CC + c0 + ci) * HW + px0 + pj];
    }
    __syncthreads();
#pragma unroll
    for (int r = 0; r < 4; r++) {
        int pj = (t >> 5) + r * 8, ci = t & 31;
        float v = tile[ci][pj];
        bf16 h = __float2bfloat16(v);
        float rem = v - __bfloat162float(h);
        size_t idx = ((size_t)b * HW + px0 + pj) * CC + c0 + ci;
        hi[idx] = h;
        lo[idx] = __float2bfloat16(rem);
    }
}

__global__ void __launch_bounds__(256) splitW_kernel(
    const float* __restrict__ W, bf16* __restrict__ hi, bf16* __restrict__ lo)
{
    int i = blockIdx.x * 256 + threadIdx.x;
    if (i < CC * CC) {
        float v = W[i];
        bf16 h = __float2bfloat16(v);
        hi[i] = h;
        lo[i] = __float2bfloat16(v - __bfloat162float(h));
    }
}

// ---------------------------------------------------------------------------
// Conv GEMM on mma.sync, cp.async 2-stage pipeline. 128x128 tile, K chunk 32.
// Epilogue: bf16 hi(/lo) outputs, permuted [bh][pp][d].
// ---------------------------------------------------------------------------
#define KPAD 40
#define STGB (4 * 128 * KPAD * 2)
#define AHI 0
#define ALO (128 * KPAD * 2)
#define BHI (2 * 128 * KPAD * 2)
#define BLO (3 * 128 * KPAD * 2)

__global__ void __launch_bounds__(256) conv_wmma_kernel(
    const bf16* __restrict__ Ah, const bf16* __restrict__ Al,
    const bf16* __restrict__ Bh, const bf16* __restrict__ Bl,
    const float* __restrict__ bias, float scale,
    bf16* __restrict__ dsth, bf16* __restrict__ dstl)
{
    extern __shared__ __align__(16) bf16 cs[];
    const uint32_t sb = smem_u32(cs);

    const int tid  = threadIdx.x;
    const int lane = tid & 31;
    const int warp = tid >> 5;
    const int wm   = warp & 3;
    const int wn   = warp >> 2;

    const int M0 = blockIdx.x * 128;
    const int o0 = blockIdx.y * 128;

    const int crow = tid >> 2, cq = tid & 3;
    const bf16* pAh = Ah + (size_t)(M0 + crow) * CC + cq * 8;
    const bf16* pAl = Al + (size_t)(M0 + crow) * CC + cq * 8;
    const bf16* pBh = Bh + (size_t)(o0 + crow) * CC + cq * 8;
    const bf16* pBl = Bl + (size_t)(o0 + crow) * CC + cq * 8;

    float acc[2][8][4];
#pragma unroll
    for (int mi = 0; mi < 2; mi++)
#pragma unroll
        for (int nf = 0; nf < 8; nf++)
#pragma unroll
            for (int k = 0; k < 4; k++) acc[mi][nf][k] = 0.f;

    const int lrow = lane & 15;
    const int lcol = (lane >> 4) * 8;

    {
#pragma unroll
        for (int r = 0; r < 2; r++) {
            const size_t go = (size_t)r * 64 * CC;
            uint32_t so = sb + ((crow + r * 64) * KPAD + cq * 8) * 2;
            cpa16(so + AHI, pAh + go);
            cpa16(so + ALO, pAl + go);
            cpa16(so + BHI, pBh + go);
            cpa16(so + BLO, pBl + go);
        }
        asm volatile("cp.async.commit_group;");
    }

    for (int ch = 0; ch < 16; ch++) {
        const int s = ch & 1;
        if (ch + 1 < 16) {
            const int k1 = (ch + 1) * 32;
            const uint32_t stb = sb + ((ch + 1) & 1) * STGB;
#pragma unroll
            for (int r = 0; r < 2; r++) {
                const size_t go = (size_t)r * 64 * CC + k1;
                uint32_t so = stb + ((crow + r * 64) * KPAD + cq * 8) * 2;
                cpa16(so + AHI, pAh + go);
                cpa16(so + ALO, pAl + go);
                cpa16(so + BHI, pBh + go);
                cpa16(so + BLO, pBl + go);
            }
            asm volatile("cp.async.commit_group;");
            asm volatile("cp.async.wait_group 1;");
        } else {
            asm volatile("cp.async.wait_group 0;");
        }
        __syncthreads();

        const uint32_t stb = sb + s * STGB;
#pragma unroll
        for (int ks = 0; ks < 2; ks++) {
            const int kc = ks * 16 + lcol;

            uint32_t a[2][2][4];
#pragma unroll
            for (int sp = 0; sp < 2; sp++)
#pragma unroll
                for (int mi = 0; mi < 2; mi++) {
                    uint32_t off = stb + (sp ? ALO : AHI) +
                                   ((wm * 32 + mi * 16 + lrow) * KPAD + kc) * 2;
                    ldmx4(a[sp][mi], off);
                }

#pragma unroll
            for (int np = 0; np < 4; np++) {
                uint32_t bh[4], bl[4];
                uint32_t offh = stb + BHI + ((wn * 64 + np * 16 + lrow) * KPAD + kc) * 2;
                uint32_t offl = stb + BLO + ((wn * 64 + np * 16 + lrow) * KPAD + kc) * 2;
                ldmx4(bh, offh);
                ldmx4(bl, offl);
#pragma unroll
                for (int mi = 0; mi < 2; mi++)
#pragma unroll
                    for (int hf = 0; hf < 2; hf++) {
                        const int nf = np * 2 + hf;
                        mma16816(acc[mi][nf], a[0][mi], bh[hf], bh[2 + hf]);
                        mma16816(acc[mi][nf], a[0][mi], bl[hf], bl[2 + hf]);
                        mma16816(acc[mi][nf], a[1][mi], bh[hf], bh[2 + hf]);
                    }
            }
        }
        __syncthreads();
    }

    // epilogue: bias+scale, bf16 split, permuted write
    const bool haveLo = (dstl != nullptr);
#pragma unroll
    for (int mi = 0; mi < 2; mi++) {
        const int m  = M0 + wm * 32 + mi * 16 + (lane >> 2);
        const int b  = m / HW;
        const int pp = m % HW;
#pragma unroll
        for (int nf = 0; nf < 8; nf++) {
            const int o = o0 + wn * 64 + nf * 8 + (lane & 3) * 2;
            const int h = o >> 6, d = o & 63;
            const float b0 = bias[o], b1 = bias[o + 1];
            float v0 = (acc[mi][nf][0] + b0) * scale;
            float v1 = (acc[mi][nf][1] + b1) * scale;
            float v2 = (acc[mi][nf][2] + b0) * scale;
            float v3 = (acc[mi][nf][3] + b1) * scale;
            size_t i0 = ((size_t)(b * NH + h) * HW + pp) * DD + d;
            size_t i1 = i0 + (size_t)8 * DD;
            bf16 h0 = __float2bfloat16(v0), h1 = __float2bfloat16(v1);
            bf16 h2 = __float2bfloat16(v2), h3 = __float2bfloat16(v3);
            *(bf162*)(dsth + i0) = bf162{h0, h1};
            *(bf162*)(dsth + i1) = bf162{h2, h3};
            if (haveLo) {
                bf16 l0 = __float2bfloat16(v0 - __bfloat162float(h0));
                bf16 l1 = __float2bfloat16(v1 - __bfloat162float(h1));
                bf16 l2 = __float2bfloat16(v2 - __bfloat162float(h2));
                bf16 l3 = __float2bfloat16(v3 - __bfloat162float(h3));
                *(bf162*)(dstl + i0) = bf162{l0, l1};
                *(bf162*)(dstl + i1) = bf162{l2, l3};
            }
        }
    }
}

// ---------------------------------------------------------------------------
// Shared mma building block: logits 96x96x64 with hi/lo A and B in SMEM.
// Warp (wm in 0..1, wn in 0..3): 3 m16-tiles x 3 n8-tiles. acc[3][3][4].
// A at aOff (hi) / aOff+13824 (lo); B at bOff / bOff+13824. Pitch 72 bf16.
// ---------------------------------------------------------------------------
#define PBF 72
#define ABUF 13824   // 96*72*2

__device__ __forceinline__ void logits_mma(
    uint32_t sb, uint32_t aOff, uint32_t bOff, int lane, int wm, int wn,
    float acc[3][3][4])
{
    const int l15 = lane & 15;
#pragma unroll
    for (int ks = 0; ks < 4; ks++) {
        const int kc = ks * 16;
        uint32_t a[2][3][4];
#pragma unroll
        for (int sp = 0; sp < 2; sp++)
#pragma unroll
            for (int mt = 0; mt < 3; mt++) {
                uint32_t addr = sb + aOff + sp * ABUF +
                    ((wm * 48 + mt * 16 + l15) * PBF + kc + (lane >> 4) * 8) * 2;
                ldmx4(a[sp][mt], addr);
            }
#pragma unroll
        for (int nt = 0; nt < 3; nt++) {
            uint32_t bh[2], bl[2];
            uint32_t ba = sb + bOff +
                ((wn * 24 + nt * 8 + (l15 & 7)) * PBF + kc + ((l15 >> 3) & 1) * 8) * 2;
            ldmx2(bh, ba);
            ldmx2(bl, ba + ABUF);
#pragma unroll
            for (int mt = 0; mt < 3; mt++) {
                mma16816(acc[mt][nt], a[0][mt], bh[0], bh[1]);
                mma16816(acc[mt][nt], a[0][mt], bl[0], bl[1]);
                mma16816(acc[mt][nt], a[1][mt], bh[0], bh[1]);
            }
        }
    }
}

// Output mma: C[96][64] = A[96][96](bf16, pitch 104) * B[96][64](bf16, pitch 72, trans)
// Warp (wm 0..1, wn 0..3): 3 m16-tiles x 2 n8-tiles (one ldmxt4 covers both).
#define PA 104

__device__ __forceinline__ void probs_mma(
    uint32_t sb, uint32_t aOff, uint32_t gOff, int lane, int wm, int wn,
    float acc[3][2][4])
{
    const int l15 = lane & 15;
#pragma unroll
    for (int ks = 0; ks < 6; ks++) {
        const int kc = ks * 16;
        uint32_t a[3][4];
#pragma unroll
        for (int mt = 0; mt < 3; mt++) {
            uint32_t addr = sb + aOff +
                ((wm * 48 + mt * 16 + l15) * PA + kc + (lane >> 4) * 8) * 2;
            ldmx4(a[mt], addr);
        }
        uint32_t bt[4];
        uint32_t ba = sb + gOff + ((kc + l15) * PBF + wn * 16 + (lane >> 4) * 8) * 2;
        ldmxt4(bt, ba);
#pragma unroll
        for (int mt = 0; mt < 3; mt++) {
            mma16816(acc[mt][0], a[mt], bt[0], bt[1]);
            mma16816(acc[mt][1], a[mt], bt[2], bt[3]);
        }
    }
}

// ---------------------------------------------------------------------------
// Kernel 2: row logits -> d_Er. Block (y, bh). mma.
// SMEM: th, tl, fh, fl [96][72] bf16 = 55296 B
// ---------------------------------------------------------------------------
__global__ void __launch_bounds__(256) erow_kernel()
{
    extern __shared__ __align__(16) char smem[];
    const uint32_t sb = smem_u32(smem);

    const int y = blockIdx.x, bh = blockIdx.y, tid = threadIdx.x;
    const int lane = tid & 31, warp = tid >> 5;

    const size_t off = ((size_t)bh * HW + y * 96) * DD;
    const bf16* srcs[4] = {d_tbh + off, d_tbl + off, d_fbh + off, d_fbl + off};
#pragma unroll
    for (int a = 0; a < 4; a++)
#pragma unroll
        for (int k = 0; k < 3; k++) {
            int idx = tid + k * 256;
            int row = idx >> 3, c = (idx & 7) * 8;
            *(uint4*)(smem + a * ABUF + (row * PBF + c) * 2) =
                *(const uint4*)(srcs[a] + (size_t)idx * 8);
        }
    __syncthreads();

    float acc[3][3][4];
#pragma unroll
    for (int mt = 0; mt < 3; mt++)
#pragma unroll
        for (int nt = 0; nt < 3; nt++)
#pragma unroll
            for (int k = 0; k < 4; k++) acc[mt][nt][k] = 0.f;

    const int wm = warp >> 2, wn = warp & 3;
    logits_mma(sb, 0, 2 * ABUF, lane, wm, wn, acc);

    float* Eb = d_Er + ((size_t)bh * HH + y) * WW * 96;
#pragma unroll
    for (int mt = 0; mt < 3; mt++)
#pragma unroll
        for (int nt = 0; nt < 3; nt++) {
            const int x0 = wm * 48 + mt * 16 + (lane >> 2);
            const int i0 = wn * 24 + nt * 8 + (lane & 3) * 2;
            *(float2*)&Eb[(size_t)x0 * 96 + i0]       = float2{acc[mt][nt][0], acc[mt][nt][1]};
            *(float2*)&Eb[(size_t)(x0 + 8) * 96 + i0] = float2{acc[mt][nt][2], acc[mt][nt][3]};
        }
}

// ---------------------------------------------------------------------------
// Kernel 3 (fused): per (x, bh): col logits (mma, SMEM) + softmax(192)
//   + emit row probs (bf16) + column output (mma) -> d_O.
// SMEM phases:
//   P1: th,tl,fh,fl [4*13824 = 55296] | Ec f32 [96][100] @55296 (38400)
//   P2: Er f32 [96][100] @0 | g bf16 [96][72] @38400
//   P3: Acol bf16 [96][104] @0
// total 93696 B
// ---------------------------------------------------------------------------
#define EC_OFF 55296
#define G_OFF  38400

__global__ void __launch_bounds__(256) fusedcol_kernel()
{
    extern __shared__ __align__(16) char smem[];
    const uint32_t sb = smem_u32(smem);

    const int x = blockIdx.x, bh = blockIdx.y, tid = threadIdx.x;
    const int lane = tid & 31, warp = tid >> 5;
    const int wm = warp >> 2, wn = warp & 3;

    // P1 load: t/f hi/lo columns (strided rows)
    {
        const size_t off = ((size_t)bh * HW + x) * DD;
        const bf16* srcs[4] = {d_tbh + off, d_tbl + off, d_fbh + off, d_fbl + off};
#pragma unroll
        for (int a = 0; a < 4; a++)
#pragma unroll
            for (int k = 0; k < 3; k++) {
                int idx = tid + k * 256;
                int row = idx >> 3, c = (idx & 7) * 8;
                *(uint4*)(smem + a * ABUF + (row * PBF + c) * 2) =
                    *(const uint4*)(srcs[a] + (size_t)row * (WW * DD) + c);
            }
    }
    __syncthreads();

    // column logits -> Ec with diagonal mask
    {
        float acc[3][3][4];
#pragma unroll
        for (int mt = 0; mt < 3; mt++)
#pragma unroll
            for (int nt = 0; nt < 3; nt++)
#pragma unroll
                for (int k = 0; k < 4; k++) acc[mt][nt][k] = 0.f;

        logits_mma(sb, 0, 2 * ABUF, lane, wm, wn, acc);

        float (*Ec)[100] = (float(*)[100])(smem + EC_OFF);
#pragma unroll
        for (int mt = 0; mt < 3; mt++)
#pragma unroll
            for (int nt = 0; nt < 3; nt++) {
                const int y0 = wm * 48 + mt * 16 + (lane >> 2);
                const int i0 = wn * 24 + nt * 8 + (lane & 3) * 2;
                Ec[y0][i0]     = (i0     == y0)     ? -INFINITY : acc[mt][nt][0];
                Ec[y0][i0 + 1] = (i0 + 1 == y0)     ? -INFINITY : acc[mt][nt][1];
                Ec[y0 + 8][i0]     = (i0     == y0 + 8) ? -INFINITY : acc[mt][nt][2];
                Ec[y0 + 8][i0 + 1] = (i0 + 1 == y0 + 8) ? -INFINITY : acc[mt][nt][3];
            }
    }
    __syncthreads();   // t/f reads done, Ec complete

    // P2 loads: Er slice + g column
    {
        float (*Er)[100] = (float(*)[100])smem;
        const float* eb = d_Er + (size_t)bh * HH * WW * 96 + (size_t)x * 96;
        for (int idx = tid; idx < 96 * 24; idx += 256) {
            int r = idx / 24, c4 = idx % 24;
            *(float4*)&Er[r][c4 * 4] =
                *(const float4*)(eb + (size_t)r * (WW * 96) + c4 * 4);
        }
        const bf16* gsrc = d_gb + ((size_t)bh * HW + x) * DD;
#pragma unroll
        for (int k = 0; k < 3; k++) {
            int idx = tid + k * 256;
            int row = idx >> 3, c = (idx & 7) * 8;
            *(uint4*)(smem + G_OFF + (row * PBF + c) * 2) =
                *(const uint4*)(gsrc + (size_t)row * (WW * DD) + c);
        }
    }
    __syncthreads();

    // softmax over concat(Er, Ec) — warp per row
    {
        float (*Er)[100] = (float(*)[100])smem;
        float (*Ec)[100] = (float(*)[100])(smem + EC_OFF);
#pragma unroll 1
        for (int rr = 0; rr < 12; rr++) {
            const int r = warp * 12 + rr;
            float vr[3], vc[3];
#pragma unroll
            for (int k = 0; k < 3; k++) { vr[k] = Er[r][lane + k * 32]; vc[k] = Ec[r][lane + k * 32]; }
            float m = -INFINITY;
#pragma unroll
            for (int k = 0; k < 3; k++) m = fmaxf(m, fmaxf(vr[k], vc[k]));
#pragma unroll
            for (int off = 16; off; off >>= 1) m = fmaxf(m, __shfl_xor_sync(0xffffffffu, m, off));
            float s = 0.f;
#pragma unroll
            for (int k = 0; k < 3; k++) {
                vr[k] = __expf(vr[k] - m); vc[k] = __expf(vc[k] - m);
                s += vr[k] + vc[k];
            }
#pragma unroll
            for (int off = 16; off; off >>= 1) s += __shfl_xor_sync(0xffffffffu, s, off);
            const float inv = 1.f / s;
#pragma unroll
            for (int k = 0; k < 3; k++) {
                Er[r][lane + k * 32] = vr[k] * inv;
                Ec[r][lane + k * 32] = vc[k] * inv;
            }
        }
    }
    __syncthreads();

    // emit row probs bf16
    {
        float (*Er)[100] = (float(*)[100])smem;
        for (int idx = tid; idx < 96 * 48; idx += 256) {
            int yv = idx / 48, i2 = idx % 48;
            float2 pr = {Er[yv][i2 * 2], Er[yv][i2 * 2 + 1]};
            *(bf162*)&d_Ar[((size_t)(bh * HH + yv) * WW + x) * 96 + i2 * 2] =
                __float22bfloat162_rn(pr);
        }
    }
    __syncthreads();   // Er reads done before Acol overwrite

    // convert col probs -> bf16 @0
    {
        float (*Ec)[100] = (float(*)[100])(smem + EC_OFF);
        bf16 (*Ac)[PA] = (bf16(*)[PA])smem;
        for (int idx = tid; idx < 96 * 48; idx += 256) {
            int yv = idx / 48, i2 = idx % 48;
            float2 pr = {Ec[yv][i2 * 2], Ec[yv][i2 * 2 + 1]};
            *(bf162*)&Ac[yv][i2 * 2] = __float22bfloat162_rn(pr);
        }
    }
    __syncthreads();

    // column output mma -> d_O
    {
        float acc[3][2][4];
#pragma unroll
        for (int mt = 0; mt < 3; mt++)
#pragma unroll
            for (int nt = 0; nt < 2; nt++)
#pragma unroll
                for (int k = 0; k < 4; k++) acc[mt][nt][k] = 0.f;

        probs_mma(sb, 0, G_OFF, lane, wm, wn, acc);

#pragma unroll
        for (int mt = 0; mt < 3; mt++)
#pragma unroll
            for (int nt = 0; nt < 2; nt++) {
                const int yv = wm * 48 + mt * 16 + (lane >> 2);
                const int d0 = wn * 16 + nt * 8 + (lane & 3) * 2;
                float* ob = d_O + ((size_t)(bh * HH + yv) * WW + x) * DD + d0;
                *(float2*)ob = float2{acc[mt][nt][0], acc[mt][nt][1]};
                *(float2*)(ob + (size_t)8 * WW * DD) = float2{acc[mt][nt][2], acc[mt][nt][3]};
            }
    }
}

// ---------------------------------------------------------------------------
// Kernel 4: row output (mma) + combine + residual. Block (y, bh).
// static SMEM: Ar [96][104] bf16 (19968) + g [96][72] bf16 (13824)
// ---------------------------------------------------------------------------
__global__ void __launch_bounds__(256) rowout_kernel(
    const float* __restrict__ v, const float* __restrict__ gamma,
    float* __restrict__ out)
{
    __shared__ __align__(16) bf16 Asm[96][PA];
    __shared__ __align__(16) bf16 gsm[96][PBF];

    const int y = blockIdx.x, bh = blockIdx.y, tid = threadIdx.x;
    const int lane = tid & 31, warp = tid >> 5;
    const int wm = warp >> 2, wn = warp & 3;

    const bf16* ab = d_Ar + ((size_t)bh * HH + y) * WW * 96;
    for (int idx = tid; idx < 96 * 12; idx += 256) {
        int row = idx / 12, c8 = idx % 12;
        *(uint4*)&Asm[row][c8 * 8] = *(const uint4*)(ab + (size_t)row * 96 + c8 * 8);
    }
    const bf16* gb = d_gb + ((size_t)bh * HH + y) * WW * DD;
#pragma unroll
    for (int k = 0; k < 3; k++) {
        int idx = tid + k * 256;
        int row = idx >> 3, c = (idx & 7) * 8;
        *(uint4*)&gsm[row][c] = *(const uint4*)(gb + (size_t)idx * 8);
    }
    __syncthreads();

    float acc[3][2][4];
#pragma unroll
    for (int mt = 0; mt < 3; mt++)
#pragma unroll
        for (int nt = 0; nt < 2; nt++)
#pragma unroll
            for (int k = 0; k < 4; k++) acc[mt][nt][k] = 0.f;

    const uint32_t sbA = smem_u32(Asm);
    const uint32_t sbG = smem_u32(gsm);
    probs_mma(sbA, 0, sbG - sbA, lane, wm, wn, acc);

    const float gam = gamma[0];
    const int b = bh >> 3, h = bh & 7;
    const float* colp = d_O + ((size_t)bh * HH + y) * WW * DD;

#pragma unroll
    for (int mt = 0; mt < 3; mt++)
#pragma unroll
        for (int nt = 0; nt < 2; nt++) {
            const int x0 = wm * 48 + mt * 16 + (lane >> 2);
            const int d0 = wn * 16 + nt * 8 + (lane & 3) * 2;
#pragma unroll
            for (int rh = 0; rh < 2; rh++) {
                const int xx = x0 + rh * 8;
                float2 cp = *(const float2*)(colp + (size_t)xx * DD + d0);
                float s0 = acc[mt][nt][rh * 2]     + cp.x;
                float s1 = acc[mt][nt][rh * 2 + 1] + cp.y;
                size_t oa0 = (((size_t)(b * CC + h * 64 + d0)) * HH + y) * WW + xx;
                size_t oa1 = oa0 + (size_t)HW;
                out[oa0] = gam * s0 + v[oa0];
                out[oa1] = gam * s1 + v[oa1];
            }
        }
}

// ---------------------------------------------------------------------------
extern "C" void kernel_launch(void* const* d_in, const int* in_sizes, int n_in,
                              void* d_out, int out_size)
{
    const float* q     = (const float*)d_in[0];
    const float* v     = (const float*)d_in[1];
    const float* Wq    = (const float*)d_in[2];
    const float* bq    = (const float*)d_in[3];
    const float* Wk    = (const float*)d_in[4];
    const float* bk    = (const float*)d_in[5];
    const float* Wv    = (const float*)d_in[6];
    const float* bv    = (const float*)d_in[7];
    const float* gamma = (const float*)d_in[8];
    float* out = (float*)d_out;

    static bf16 *pAqh = nullptr, *pAql, *pAvh, *pAvl, *pWh, *pWl;
    static bf16 *pTh, *pTl, *pFh, *pFl, *pG;
    if (!pAqh) {
        cudaGetSymbolAddress((void**)&pAqh, d_Aq_hi);
        cudaGetSymbolAddress((void**)&pAql, d_Aq_lo);
        cudaGetSymbolAddress((void**)&pAvh, d_Av_hi);
        cudaGetSymbolAddress((void**)&pAvl, d_Av_lo);
        cudaGetSymbolAddress((void**)&pWh,  d_Wh);
        cudaGetSymbolAddress((void**)&pWl,  d_Wl);
        cudaGetSymbolAddress((void**)&pTh,  d_tbh);
        cudaGetSymbolAddress((void**)&pTl,  d_tbl);
        cudaGetSymbolAddress((void**)&pFh,  d_fbh);
        cudaGetSymbolAddress((void**)&pFl,  d_fbl);
        cudaGetSymbolAddress((void**)&pG,   d_gb);
    }

    const int smConv = 2 * STGB;            // 81920
    const int smE    = 4 * ABUF;            // 55296
    const int smF    = EC_OFF + 96 * 100 * 4; // 93696
    static bool attrs_set = false;
    if (!attrs_set) {
        cudaFuncSetAttribute(conv_wmma_kernel, cudaFuncAttributeMaxDynamicSharedMemorySize, smConv);
        cudaFuncSetAttribute(erow_kernel,      cudaFuncAttributeMaxDynamicSharedMemorySize, smE);
        cudaFuncSetAttribute(fusedcol_kernel,  cudaFuncAttributeMaxDynamicSharedMemorySize, smF);
        attrs_set = true;
    }

    // Prepasses
    dim3 spGrid(HW / 32, CC / 32, BB);
    splitX_kernel<<<spGrid, 256>>>(q, pAqh, pAql);
    splitX_kernel<<<spGrid, 256>>>(v, pAvh, pAvl);
    splitW_kernel<<<(CC * CC + 255) / 256, 256>>>(Wq, pWh, pWl);
    splitW_kernel<<<(CC * CC + 255) / 256, 256>>>(Wk, pWh + CC * CC, pWl + CC * CC);
    splitW_kernel<<<(CC * CC + 255) / 256, 256>>>(Wv, pWh + 2 * CC * CC, pWl + 2 * CC * CC);

    // Conv GEMMs
    dim3 cg(MTOT / 128, CC / 128);
    conv_wmma_kernel<<<cg, 256, smConv>>>(pAqh, pAql, pWh,              pWl,              bq, SCALING, pTh, pTl);
    conv_wmma_kernel<<<cg, 256, smConv>>>(pAqh, pAql, pWh + CC * CC,     pWl + CC * CC,     bk, 1.0f,    pFh, pFl);
    conv_wmma_kernel<<<cg, 256, smConv>>>(pAvh, pAvl, pWh + 2 * CC * CC, pWl + 2 * CC * CC, bv, 1.0f,    pG,  nullptr);

    // Attention (all matmuls on tensor cores)
    dim3 attnGrid(96, BHD);
    erow_kernel<<<attnGrid, 256, smE>>>();
    fusedcol_kernel<<<attnGrid, 256, smF>>>();
    rowout_kernel<<<attnGrid, 256>>>(v, gamma, out);
}

// round 8
// speedup vs baseline: 9.1372x; 1.7039x over previous
#include <cuda_runtime.h>
#include <cuda_bf16.h>
#include <math.h>
#include <cstdint>

#define BB 4
#define NH 8
#define BHD 32
#define HH 96
#define WW 96
#define CC 512
#define DD 64
#define HW 9216
#define MTOT (BB * HW)      // 36864
#define SCALING 0.125f

typedef __nv_bfloat16 bf16;
typedef __nv_bfloat162 bf162;

// ---------------------------------------------------------------------------
// Device-global scratch
// ---------------------------------------------------------------------------
__device__ float d_Er[(size_t)BHD * HW * 96];   // row logits (fp32)
__device__ bf16  d_Ar[(size_t)BHD * HW * 96];   // row probs (bf16)
__device__ float d_O [(size_t)BHD * HW * DD];   // column partial (fp32)
// conv outputs (attention operands, bf16, [bh][px][d])
__device__ bf16 d_tb[(size_t)BHD * HW * DD];
__device__ bf16 d_fb[(size_t)BHD * HW * DD];
__device__ bf16 d_gb[(size_t)BHD * HW * DD];
// bf16 GEMM inputs, K-major [m][c]
__device__ bf16 d_Aq[(size_t)MTOT * CC];
__device__ bf16 d_Av[(size_t)MTOT * CC];
__device__ bf16 d_W [3 * CC * CC];

// ---------------------------------------------------------------------------
// Helpers (generic PTX: sm_80+ features only)
// ---------------------------------------------------------------------------
__device__ __forceinline__ uint32_t smem_u32(const void* p) {
    uint32_t a;
    asm("{ .reg .u64 t; cvta.to.shared.u64 t, %1; cvt.u32.u64 %0, t; }" : "=r"(a) : "l"(p));
    return a;
}
__device__ __forceinline__ void cpa16(uint32_t d, const void* s) {
    asm volatile("cp.async.ca.shared.global [%0], [%1], 16;" :: "r"(d), "l"(s));
}
__device__ __forceinline__ void ldmx4(uint32_t* r, uint32_t addr) {
    asm volatile("ldmatrix.sync.aligned.m8n8.x4.shared.b16 {%0,%1,%2,%3}, [%4];"
        : "=r"(r[0]), "=r"(r[1]), "=r"(r[2]), "=r"(r[3]) : "r"(addr));
}
__device__ __forceinline__ void ldmxt4(uint32_t* r, uint32_t addr) {
    asm volatile("ldmatrix.sync.aligned.m8n8.x4.trans.shared.b16 {%0,%1,%2,%3}, [%4];"
        : "=r"(r[0]), "=r"(r[1]), "=r"(r[2]), "=r"(r[3]) : "r"(addr));
}
__device__ __forceinline__ void ldmx2(uint32_t* r, uint32_t addr) {
    asm volatile("ldmatrix.sync.aligned.m8n8.x2.shared.b16 {%0,%1}, [%2];"
        : "=r"(r[0]), "=r"(r[1]) : "r"(addr));
}
__device__ __forceinline__ void mma16816(float* c, const uint32_t* a,
                                         uint32_t b0, uint32_t b1) {
    asm volatile(
        "mma.sync.aligned.m16n8k16.row.col.f32.bf16.bf16.f32 "
        "{%0,%1,%2,%3}, {%4,%5,%6,%7}, {%8,%9}, {%0,%1,%2,%3};"
        : "+f"(c[0]), "+f"(c[1]), "+f"(c[2]), "+f"(c[3])
        : "r"(a[0]), "r"(a[1]), "r"(a[2]), "r"(a[3]), "r"(b0), "r"(b1));
}

// ---------------------------------------------------------------------------
// Prepass A: transpose + bf16 convert  X[b][c][px] -> A [m][c]
// ---------------------------------------------------------------------------
__global__ void __launch_bounds__(256) toA_kernel(
    const float* __restrict__ X, bf16* __restrict__ dst)
{
    __shared__ float tile[32][33];
    const int t   = threadIdx.x;
    const int px0 = blockIdx.x * 32;
    const int c0  = blockIdx.y * 32;
    const int b   = blockIdx.z;

#pragma unroll
    for (int r = 0; r < 4; r++) {
        int ci = (t >> 5) + r * 8, pj = t & 31;
        tile[ci][pj] = X[((size_t)b * CC + c0 + ci) * HW + px0 + pj];
    }
    __syncthreads();
#pragma unroll
    for (int r = 0; r < 4; r++) {
        int pj = (t >> 5) + r * 8, ci = t & 31;
        dst[((size_t)b * HW + px0 + pj) * CC + c0 + ci] = __float2bfloat16(tile[ci][pj]);
    }
}

__global__ void __launch_bounds__(256) toW_kernel(
    const float* __restrict__ W, bf16* __restrict__ dst)
{
    int i = blockIdx.x * 256 + threadIdx.x;
    if (i < CC * CC) dst[i] = __float2bfloat16(W[i]);
}

// ---------------------------------------------------------------------------
// Conv GEMM on mma.sync, cp.async 3-stage pipeline. 128x128 tile, K chunk 32.
// Plain bf16, fp32 accum. Epilogue: bf16 output, permuted [bh][pp][d].
// ---------------------------------------------------------------------------
#define KPAD 40
#define AOFF 0
#define BOFF (128 * KPAD * 2)       // 10240
#define STGB (2 * 128 * KPAD * 2)   // 20480

__global__ void __launch_bounds__(256) conv_wmma_kernel(
    const bf16* __restrict__ A, const bf16* __restrict__ B,
    const float* __restrict__ bias, float scale, bf16* __restrict__ dst)
{
    extern __shared__ __align__(16) bf16 cs[];
    const uint32_t sb = smem_u32(cs);

    const int tid  = threadIdx.x;
    const int lane = tid & 31;
    const int warp = tid >> 5;
    const int wm   = warp & 3;   // m 32-row sub-block
    const int wn   = warp >> 2;  // n 64-col sub-block

    const int M0 = blockIdx.x * 128;
    const int o0 = blockIdx.y * 128;

    // copy mapping: row = tid>>2 (0..63, +64 second pass), cseg = tid&3
    // (4 segments x 8 bf16 = full 32-wide chunk per row)
    const int crow = tid >> 2, cseg = tid & 3;
    const bf16* pA = A + (size_t)(M0 + crow) * CC + cseg * 8;
    const bf16* pB = B + (size_t)(o0 + crow) * CC + cseg * 8;
    const uint32_t sdst = (crow * KPAD + cseg * 8) * 2;
    const uint32_t rstep = 64 * KPAD * 2;

    float acc[2][8][4];
#pragma unroll
    for (int mi = 0; mi < 2; mi++)
#pragma unroll
        for (int nf = 0; nf < 8; nf++)
#pragma unroll
            for (int k = 0; k < 4; k++) acc[mi][nf][k] = 0.f;

    const int lrow = lane & 15;
    const int lsel = (lane >> 4) * 8;

    // prologue: stage chunks 0 and 1
#pragma unroll
    for (int p = 0; p < 2; p++) {
        uint32_t so = sb + p * STGB + sdst;
#pragma unroll
        for (int r = 0; r < 2; r++) {
            const size_t go = (size_t)r * 64 * CC + p * 32;
            cpa16(so + AOFF + r * rstep, pA + go);
            cpa16(so + BOFF + r * rstep, pB + go);
        }
        asm volatile("cp.async.commit_group;");
    }

    for (int ch = 0; ch < 16; ch++) {
        if (ch + 2 < 16) {
            uint32_t so = sb + ((ch + 2) % 3) * STGB + sdst;
#pragma unroll
            for (int r = 0; r < 2; r++) {
                const size_t go = (size_t)r * 64 * CC + (ch + 2) * 32;
                cpa16(so + AOFF + r * rstep, pA + go);
                cpa16(so + BOFF + r * rstep, pB + go);
            }
            asm volatile("cp.async.commit_group;");
            asm volatile("cp.async.wait_group 2;");
        } else if (ch + 1 < 16) {
            asm volatile("cp.async.wait_group 1;");
        } else {
            asm volatile("cp.async.wait_group 0;");
        }
        __syncthreads();

        const uint32_t stb = sb + (ch % 3) * STGB;
#pragma unroll
        for (int ks = 0; ks < 2; ks++) {
            const int kc = ks * 16 + lsel;
            uint32_t a[2][4];
#pragma unroll
            for (int mi = 0; mi < 2; mi++)
                ldmx4(a[mi], stb + AOFF + ((wm * 32 + mi * 16 + lrow) * KPAD + kc) * 2);
#pragma unroll
            for (int np = 0; np < 4; np++) {
                uint32_t b[4];
                ldmx4(b, stb + BOFF + ((wn * 64 + np * 16 + lrow) * KPAD + kc) * 2);
#pragma unroll
                for (int mi = 0; mi < 2; mi++)
#pragma unroll
                    for (int hf = 0; hf < 2; hf++)
                        mma16816(acc[mi][np * 2 + hf], a[mi], b[hf], b[2 + hf]);
            }
        }
        __syncthreads();
    }

    // epilogue: bias+scale, bf16, permuted write
#pragma unroll
    for (int mi = 0; mi < 2; mi++) {
        const int m  = M0 + wm * 32 + mi * 16 + (lane >> 2);
        const int b  = m / HW;
        const int pp = m % HW;
#pragma unroll
        for (int nf = 0; nf < 8; nf++) {
            const int o = o0 + wn * 64 + nf * 8 + (lane & 3) * 2;
            const int h = o >> 6, d = o & 63;
            const float b0 = bias[o], b1 = bias[o + 1];
            size_t i0 = ((size_t)(b * NH + h) * HW + pp) * DD + d;
            size_t i1 = i0 + (size_t)8 * DD;
            *(bf162*)(dst + i0) = bf162{
                __float2bfloat16((acc[mi][nf][0] + b0) * scale),
                __float2bfloat16((acc[mi][nf][1] + b1) * scale)};
            *(bf162*)(dst + i1) = bf162{
                __float2bfloat16((acc[mi][nf][2] + b0) * scale),
                __float2bfloat16((acc[mi][nf][3] + b1) * scale)};
        }
    }
}

// ---------------------------------------------------------------------------
// Logits mma: C[96][96] = A[96][64] * B[96][64]^T, bf16, pitch 72.
// Warp (wm 0..1, wn 0..3): 3 m16 x 3 n8 tiles.
// ---------------------------------------------------------------------------
#define PBF 72
#define ABUF 13824   // 96*72*2

__device__ __forceinline__ void logits_mma(
    uint32_t sb, uint32_t aOff, uint32_t bOff, int lane, int wm, int wn,
    float acc[3][3][4])
{
    const int l15 = lane & 15;
#pragma unroll
    for (int ks = 0; ks < 4; ks++) {
        const int kc = ks * 16;
        uint32_t a[3][4];
#pragma unroll
        for (int mt = 0; mt < 3; mt++)
            ldmx4(a[mt], sb + aOff +
                ((wm * 48 + mt * 16 + l15) * PBF + kc + (lane >> 4) * 8) * 2);
#pragma unroll
        for (int nt = 0; nt < 3; nt++) {
            uint32_t b[2];
            ldmx2(b, sb + bOff +
                ((wn * 24 + nt * 8 + (l15 & 7)) * PBF + kc + ((l15 >> 3) & 1) * 8) * 2);
#pragma unroll
            for (int mt = 0; mt < 3; mt++)
                mma16816(acc[mt][nt], a[mt], b[0], b[1]);
        }
    }
}

// Output mma: C[96][64] = A[96][96](pitch 104) * B[96][64](pitch 72, trans)
#define PA 104

__device__ __forceinline__ void probs_mma(
    uint32_t sb, uint32_t aOff, uint32_t gOff, int lane, int wm, int wn,
    float acc[3][2][4])
{
    const int l15 = lane & 15;
#pragma unroll
    for (int ks = 0; ks < 6; ks++) {
        const int kc = ks * 16;
        uint32_t a[3][4];
#pragma unroll
        for (int mt = 0; mt < 3; mt++)
            ldmx4(a[mt], sb + aOff +
                ((wm * 48 + mt * 16 + l15) * PA + kc + (lane >> 4) * 8) * 2);
        uint32_t bt[4];
        ldmxt4(bt, sb + gOff + ((kc + l15) * PBF + wn * 16 + (lane >> 4) * 8) * 2);
#pragma unroll
        for (int mt = 0; mt < 3; mt++) {
            mma16816(acc[mt][0], a[mt], bt[0], bt[1]);
            mma16816(acc[mt][1], a[mt], bt[2], bt[3]);
        }
    }
}

// ---------------------------------------------------------------------------
// Kernel 2: row logits -> d_Er. Block (y, bh). SMEM: t, f [96][72] = 27648 B
// ---------------------------------------------------------------------------
__global__ void __launch_bounds__(256) erow_kernel()
{
    extern __shared__ __align__(16) char smem[];
    const uint32_t sb = smem_u32(smem);

    const int y = blockIdx.x, bh = blockIdx.y, tid = threadIdx.x;
    const int lane = tid & 31, warp = tid >> 5;

    const size_t off = ((size_t)bh * HW + y * 96) * DD;
    const bf16* srcs[2] = {d_tb + off, d_fb + off};
#pragma unroll
    for (int a = 0; a < 2; a++)
#pragma unroll
        for (int k = 0; k < 3; k++) {
            int idx = tid + k * 256;
            int row = idx >> 3, c = (idx & 7) * 8;
            *(uint4*)(smem + a * ABUF + (row * PBF + c) * 2) =
                *(const uint4*)(srcs[a] + (size_t)idx * 8);
        }
    __syncthreads();

    float acc[3][3][4];
#pragma unroll
    for (int mt = 0; mt < 3; mt++)
#pragma unroll
        for (int nt = 0; nt < 3; nt++)
#pragma unroll
            for (int k = 0; k < 4; k++) acc[mt][nt][k] = 0.f;

    const int wm = warp >> 2, wn = warp & 3;
    logits_mma(sb, 0, ABUF, lane, wm, wn, acc);

    float* Eb = d_Er + ((size_t)bh * HH + y) * WW * 96;
#pragma unroll
    for (int mt = 0; mt < 3; mt++)
#pragma unroll
        for (int nt = 0; nt < 3; nt++) {
            const int x0 = wm * 48 + mt * 16 + (lane >> 2);
            const int i0 = wn * 24 + nt * 8 + (lane & 3) * 2;
            *(float2*)&Eb[(size_t)x0 * 96 + i0]       = float2{acc[mt][nt][0], acc[mt][nt][1]};
            *(float2*)&Eb[(size_t)(x0 + 8) * 96 + i0] = float2{acc[mt][nt][2], acc[mt][nt][3]};
        }
}

// ---------------------------------------------------------------------------
// Kernel 3 (fused): per (x, bh): col logits (mma, SMEM) + softmax(192)
//   + emit row probs (bf16) + column output (mma) -> d_O.
// SMEM phases:
//   P1: t@0, f@13824 (27648) | Ec f32 [96][100] @38400 (38400)
//   P2: Er f32 [96][100] @0 | g bf16 [96][72] @76800 (13824)
//   P3: Acol bf16 [96][104] @0
// total 90624 B
// ---------------------------------------------------------------------------
#define EC_OFF 38400
#define G_OFF  76800

__global__ void __launch_bounds__(256) fusedcol_kernel()
{
    extern __shared__ __align__(16) char smem[];
    const uint32_t sb = smem_u32(smem);

    const int x = blockIdx.x, bh = blockIdx.y, tid = threadIdx.x;
    const int lane = tid & 31, warp = tid >> 5;
    const int wm = warp >> 2, wn = warp & 3;

    // P1 load: t/f columns (row stride WW*DD)
    {
        const size_t off = ((size_t)bh * HW + x) * DD;
        const bf16* srcs[2] = {d_tb + off, d_fb + off};
#pragma unroll
        for (int a = 0; a < 2; a++)
#pragma unroll
            for (int k = 0; k < 3; k++) {
                int idx = tid + k * 256;
                int row = idx >> 3, c = (idx & 7) * 8;
                *(uint4*)(smem + a * ABUF + (row * PBF + c) * 2) =
                    *(const uint4*)(srcs[a] + (size_t)row * (WW * DD) + c);
            }
    }
    __syncthreads();

    // column logits -> Ec with diagonal mask
    {
        float acc[3][3][4];
#pragma unroll
        for (int mt = 0; mt < 3; mt++)
#pragma unroll
            for (int nt = 0; nt < 3; nt++)
#pragma unroll
                for (int k = 0; k < 4; k++) acc[mt][nt][k] = 0.f;

        logits_mma(sb, 0, ABUF, lane, wm, wn, acc);

        float (*Ec)[100] = (float(*)[100])(smem + EC_OFF);
#pragma unroll
        for (int mt = 0; mt < 3; mt++)
#pragma unroll
            for (int nt = 0; nt < 3; nt++) {
                const int y0 = wm * 48 + mt * 16 + (lane >> 2);
                const int i0 = wn * 24 + nt * 8 + (lane & 3) * 2;
                Ec[y0][i0]     = (i0     == y0)     ? -INFINITY : acc[mt][nt][0];
                Ec[y0][i0 + 1] = (i0 + 1 == y0)     ? -INFINITY : acc[mt][nt][1];
                Ec[y0 + 8][i0]     = (i0     == y0 + 8) ? -INFINITY : acc[mt][nt][2];
                Ec[y0 + 8][i0 + 1] = (i0 + 1 == y0 + 8) ? -INFINITY : acc[mt][nt][3];
            }
    }
    __syncthreads();   // t/f reads done, Ec complete

    // P2 loads: Er slice + g column
    {
        float (*Er)[100] = (float(*)[100])smem;
        const float* eb = d_Er + (size_t)bh * HH * WW * 96 + (size_t)x * 96;
        for (int idx = tid; idx < 96 * 24; idx += 256) {
            int r = idx / 24, c4 = idx % 24;
            *(float4*)&Er[r][c4 * 4] =
                *(const float4*)(eb + (size_t)r * (WW * 96) + c4 * 4);
        }
        const bf16* gsrc = d_gb + ((size_t)bh * HW + x) * DD;
#pragma unroll
        for (int k = 0; k < 3; k++) {
            int idx = tid + k * 256;
            int row = idx >> 3, c = (idx & 7) * 8;
            *(uint4*)(smem + G_OFF + (row * PBF + c) * 2) =
                *(const uint4*)(gsrc + (size_t)row * (WW * DD) + c);
        }
    }
    __syncthreads();

    // softmax over concat(Er, Ec) — warp per row
    {
        float (*Er)[100] = (float(*)[100])smem;
        float (*Ec)[100] = (float(*)[100])(smem + EC_OFF);
#pragma unroll 1
        for (int rr = 0; rr < 12; rr++) {
            const int r = warp * 12 + rr;
            float vr[3], vc[3];
#pragma unroll
            for (int k = 0; k < 3; k++) { vr[k] = Er[r][lane + k * 32]; vc[k] = Ec[r][lane + k * 32]; }
            float m = -INFINITY;
#pragma unroll
            for (int k = 0; k < 3; k++) m = fmaxf(m, fmaxf(vr[k], vc[k]));
#pragma unroll
            for (int off = 16; off; off >>= 1) m = fmaxf(m, __shfl_xor_sync(0xffffffffu, m, off));
            float s = 0.f;
#pragma unroll
            for (int k = 0; k < 3; k++) {
                vr[k] = __expf(vr[k] - m); vc[k] = __expf(vc[k] - m);
                s += vr[k] + vc[k];
            }
#pragma unroll
            for (int off = 16; off; off >>= 1) s += __shfl_xor_sync(0xffffffffu, s, off);
            const float inv = 1.f / s;
#pragma unroll
            for (int k = 0; k < 3; k++) {
                Er[r][lane + k * 32] = vr[k] * inv;
                Ec[r][lane + k * 32] = vc[k] * inv;
            }
        }
    }
    __syncthreads();

    // emit row probs bf16
    {
        float (*Er)[100] = (float(*)[100])smem;
        for (int idx = tid; idx < 96 * 48; idx += 256) {
            int yv = idx / 48, i2 = idx % 48;
            float2 pr = {Er[yv][i2 * 2], Er[yv][i2 * 2 + 1]};
            *(bf162*)&d_Ar[((size_t)(bh * HH + yv) * WW + x) * 96 + i2 * 2] =
                __float22bfloat162_rn(pr);
        }
    }
    __syncthreads();   // Er reads done before Acol overwrite

    // convert col probs -> bf16 @0
    {
        float (*Ec)[100] = (float(*)[100])(smem + EC_OFF);
        bf16 (*Ac)[PA] = (bf16(*)[PA])smem;
        for (int idx = tid; idx < 96 * 48; idx += 256) {
            int yv = idx / 48, i2 = idx % 48;
            float2 pr = {Ec[yv][i2 * 2], Ec[yv][i2 * 2 + 1]};
            *(bf162*)&Ac[yv][i2 * 2] = __float22bfloat162_rn(pr);
        }
    }
    __syncthreads();

    // column output mma -> d_O
    {
        float acc[3][2][4];
#pragma unroll
        for (int mt = 0; mt < 3; mt++)
#pragma unroll
            for (int nt = 0; nt < 2; nt++)
#pragma unroll
                for (int k = 0; k < 4; k++) acc[mt][nt][k] = 0.f;

        probs_mma(sb, 0, G_OFF, lane, wm, wn, acc);

#pragma unroll
        for (int mt = 0; mt < 3; mt++)
#pragma unroll
            for (int nt = 0; nt < 2; nt++) {
                const int yv = wm * 48 + mt * 16 + (lane >> 2);
                const int d0 = wn * 16 + nt * 8 + (lane & 3) * 2;
                float* ob = d_O + ((size_t)(bh * HH + yv) * WW + x) * DD + d0;
                *(float2*)ob = float2{acc[mt][nt][0], acc[mt][nt][1]};
                *(float2*)(ob + (size_t)8 * WW * DD) = float2{acc[mt][nt][2], acc[mt][nt][3]};
            }
    }
}

// ---------------------------------------------------------------------------
// Kernel 4: row output (mma) + combine + residual. Block (y, bh).
// ---------------------------------------------------------------------------
__global__ void __launch_bounds__(256) rowout_kernel(
    const float* __restrict__ v, const float* __restrict__ gamma,
    float* __restrict__ out)
{
    __shared__ __align__(16) bf16 Asm[96][PA];
    __shared__ __align__(16) bf16 gsm[96][PBF];

    const int y = blockIdx.x, bh = blockIdx.y, tid = threadIdx.x;
    const int lane = tid & 31, warp = tid >> 5;
    const int wm = warp >> 2, wn = warp & 3;

    const bf16* ab = d_Ar + ((size_t)bh * HH + y) * WW * 96;
    for (int idx = tid; idx < 96 * 12; idx += 256) {
        int row = idx / 12, c8 = idx % 12;
        *(uint4*)&Asm[row][c8 * 8] = *(const uint4*)(ab + (size_t)row * 96 + c8 * 8);
    }
    const bf16* gb = d_gb + ((size_t)bh * HH + y) * WW * DD;
#pragma unroll
    for (int k = 0; k < 3; k++) {
        int idx = tid + k * 256;
        int row = idx >> 3, c = (idx & 7) * 8;
        *(uint4*)&gsm[row][c] = *(const uint4*)(gb + (size_t)idx * 8);
    }
    __syncthreads();

    float acc[3][2][4];
#pragma unroll
    for (int mt = 0; mt < 3; mt++)
#pragma unroll
        for (int nt = 0; nt < 2; nt++)
#pragma unroll
            for (int k = 0; k < 4; k++) acc[mt][nt][k] = 0.f;

    const uint32_t sbA = smem_u32(Asm);
    const uint32_t sbG = smem_u32(gsm);
    probs_mma(sbA, 0, sbG - sbA, lane, wm, wn, acc);

    const float gam = gamma[0];
    const int b = bh >> 3, h = bh & 7;
    const float* colp = d_O + ((size_t)bh * HH + y) * WW * DD;

#pragma unroll
    for (int mt = 0; mt < 3; mt++)
#pragma unroll
        for (int nt = 0; nt < 2; nt++) {
            const int x0 = wm * 48 + mt * 16 + (lane >> 2);
            const int d0 = wn * 16 + nt * 8 + (lane & 3) * 2;
#pragma unroll
            for (int rh = 0; rh < 2; rh++) {
                const int xx = x0 + rh * 8;
                float2 cp = *(const float2*)(colp + (size_t)xx * DD + d0);
                float s0 = acc[mt][nt][rh * 2]     + cp.x;
                float s1 = acc[mt][nt][rh * 2 + 1] + cp.y;
                size_t oa0 = (((size_t)(b * CC + h * 64 + d0)) * HH + y) * WW + xx;
                size_t oa1 = oa0 + (size_t)HW;
                out[oa0] = gam * s0 + v[oa0];
                out[oa1] = gam * s1 + v[oa1];
            }
        }
}

// ---------------------------------------------------------------------------
extern "C" void kernel_launch(void* const* d_in, const int* in_sizes, int n_in,
                              void* d_out, int out_size)
{
    const float* q     = (const float*)d_in[0];
    const float* v     = (const float*)d_in[1];
    const float* Wq    = (const float*)d_in[2];
    const float* bq    = (const float*)d_in[3];
    const float* Wk    = (const float*)d_in[4];
    const float* bk    = (const float*)d_in[5];
    const float* Wv    = (const float*)d_in[6];
    const float* bv    = (const float*)d_in[7];
    const float* gamma = (const float*)d_in[8];
    float* out = (float*)d_out;

    static bf16 *pAq = nullptr, *pAv, *pW, *pT, *pF, *pG;
    if (!pAq) {
        cudaGetSymbolAddress((void**)&pAq, d_Aq);
        cudaGetSymbolAddress((void**)&pAv, d_Av);
        cudaGetSymbolAddress((void**)&pW,  d_W);
        cudaGetSymbolAddress((void**)&pT,  d_tb);
        cudaGetSymbolAddress((void**)&pF,  d_fb);
        cudaGetSymbolAddress((void**)&pG,  d_gb);
    }

    const int smConv = 3 * STGB;    // 61440
    const int smE    = 2 * ABUF;    // 27648
    const int smF    = G_OFF + ABUF; // 90624
    static bool attrs_set = false;
    if (!attrs_set) {
        cudaFuncSetAttribute(conv_wmma_kernel, cudaFuncAttributeMaxDynamicSharedMemorySize, smConv);
        cudaFuncSetAttribute(erow_kernel,      cudaFuncAttributeMaxDynamicSharedMemorySize, smE);
        cudaFuncSetAttribute(fusedcol_kernel,  cudaFuncAttributeMaxDynamicSharedMemorySize, smF);
        attrs_set = true;
    }

    // Prepasses
    dim3 spGrid(HW / 32, CC / 32, BB);
    toA_kernel<<<spGrid, 256>>>(q, pAq);
    toA_kernel<<<spGrid, 256>>>(v, pAv);
    toW_kernel<<<(CC * CC + 255) / 256, 256>>>(Wq, pW);
    toW_kernel<<<(CC * CC + 255) / 256, 256>>>(Wk, pW + CC * CC);
    toW_kernel<<<(CC * CC + 255) / 256, 256>>>(Wv, pW + 2 * CC * CC);

    // Conv GEMMs
    dim3 cg(MTOT / 128, CC / 128);
    conv_wmma_kernel<<<cg, 256, smConv>>>(pAq, pW,              bq, SCALING, pT);
    conv_wmma_kernel<<<cg, 256, smConv>>>(pAq, pW + CC * CC,     bk, 1.0f,    pF);
    conv_wmma_kernel<<<cg, 256, smConv>>>(pAv, pW + 2 * CC * CC, bv, 1.0f,    pG);

    // Attention
    dim3 attnGrid(96, BHD);
    erow_kernel<<<attnGrid, 256, smE>>>();
    fusedcol_kernel<<<attnGrid, 256, smF>>>();
    rowout_kernel<<<attnGrid, 256>>>(v, gamma, out);
}

// round 10
// speedup vs baseline: 9.6306x; 1.0540x over previous
#include <cuda_runtime.h>
#include <cuda_bf16.h>
#include <math.h>
#include <cstdint>

#define BB 4
#define NH 8
#define BHD 32
#define HH 96
#define WW 96
#define CC 512
#define DD 64
#define HW 9216
#define MTOT (BB * HW)      // 36864
#define SCALING 0.125f

typedef __nv_bfloat16 bf16;
typedef __nv_bfloat162 bf162;

// ---------------------------------------------------------------------------
// Device-global scratch
// ---------------------------------------------------------------------------
__device__ float d_Er[(size_t)BHD * HW * 96];   // row logits (fp32)
__device__ bf16  d_Ar[(size_t)BHD * HW * 96];   // row probs (bf16)
__device__ float d_O [(size_t)BHD * HW * DD];   // column partial (fp32)
// conv outputs (attention operands, bf16, [bh][px][d])
__device__ bf16 d_tb[(size_t)BHD * HW * DD];
__device__ bf16 d_fb[(size_t)BHD * HW * DD];
__device__ bf16 d_gb[(size_t)BHD * HW * DD];
// bf16 GEMM inputs, K-major [m][c]
__device__ bf16 d_Aq[(size_t)MTOT * CC];
__device__ bf16 d_Av[(size_t)MTOT * CC];
__device__ bf16 d_W [3 * CC * CC];

// ---------------------------------------------------------------------------
// Helpers (generic PTX: sm_80+ features only)
// ---------------------------------------------------------------------------
__device__ __forceinline__ uint32_t smem_u32(const void* p) {
    uint32_t a;
    asm("{ .reg .u64 t; cvta.to.shared.u64 t, %1; cvt.u32.u64 %0, t; }" : "=r"(a) : "l"(p));
    return a;
}
__device__ __forceinline__ void cpa16(uint32_t d, const void* s) {
    asm volatile("cp.async.ca.shared.global [%0], [%1], 16;" :: "r"(d), "l"(s));
}
__device__ __forceinline__ void ldmx4(uint32_t* r, uint32_t addr) {
    asm volatile("ldmatrix.sync.aligned.m8n8.x4.shared.b16 {%0,%1,%2,%3}, [%4];"
        : "=r"(r[0]), "=r"(r[1]), "=r"(r[2]), "=r"(r[3]) : "r"(addr));
}
__device__ __forceinline__ void ldmxt4(uint32_t* r, uint32_t addr) {
    asm volatile("ldmatrix.sync.aligned.m8n8.x4.trans.shared.b16 {%0,%1,%2,%3}, [%4];"
        : "=r"(r[0]), "=r"(r[1]), "=r"(r[2]), "=r"(r[3]) : "r"(addr));
}
__device__ __forceinline__ void ldmx2(uint32_t* r, uint32_t addr) {
    asm volatile("ldmatrix.sync.aligned.m8n8.x2.shared.b16 {%0,%1}, [%2];"
        : "=r"(r[0]), "=r"(r[1]) : "r"(addr));
}
__device__ __forceinline__ void mma16816(float* c, const uint32_t* a,
                                         uint32_t b0, uint32_t b1) {
    asm volatile(
        "mma.sync.aligned.m16n8k16.row.col.f32.bf16.bf16.f32 "
        "{%0,%1,%2,%3}, {%4,%5,%6,%7}, {%8,%9}, {%0,%1,%2,%3};"
        : "+f"(c[0]), "+f"(c[1]), "+f"(c[2]), "+f"(c[3])
        : "r"(a[0]), "r"(a[1]), "r"(a[2]), "r"(a[3]), "r"(b0), "r"(b1));
}

// ---------------------------------------------------------------------------
// Prepass A: transpose + bf16 convert  X[b][c][px] -> A [m][c]  (q and v)
// ---------------------------------------------------------------------------
__global__ void __launch_bounds__(256) toA_kernel(
    const float* __restrict__ Xq, const float* __restrict__ Xv,
    bf16* __restrict__ dq, bf16* __restrict__ dv)
{
    __shared__ float tile[32][33];
    const int t   = threadIdx.x;
    const int px0 = blockIdx.x * 32;
    const int c0  = blockIdx.y * 32;
    const int bz  = blockIdx.z;          // 0..7
    const float* X = (bz < 4) ? Xq : Xv;
    bf16* dst      = (bz < 4) ? dq : dv;
    const int b    = bz & 3;

#pragma unroll
    for (int r = 0; r < 4; r++) {
        int ci = (t >> 5) + r * 8, pj = t & 31;
        tile[ci][pj] = X[((size_t)b * CC + c0 + ci) * HW + px0 + pj];
    }
    __syncthreads();
#pragma unroll
    for (int r = 0; r < 4; r++) {
        int pj = (t >> 5) + r * 8, ci = t & 31;
        dst[((size_t)b * HW + px0 + pj) * CC + c0 + ci] = __float2bfloat16(tile[ci][pj]);
    }
}

__global__ void __launch_bounds__(256) toW_kernel(
    const float* __restrict__ W0, const float* __restrict__ W1,
    const float* __restrict__ W2, bf16* __restrict__ dst)
{
    const int w = blockIdx.y;
    const float* W = (w == 0) ? W0 : (w == 1) ? W1 : W2;
    int i = blockIdx.x * 256 + threadIdx.x;
    if (i < CC * CC) dst[(size_t)w * CC * CC + i] = __float2bfloat16(W[i]);
}

// ---------------------------------------------------------------------------
// Conv GEMM on mma.sync, cp.async 3-stage pipeline. 128x128 tile, K chunk 32.
// ---------------------------------------------------------------------------
#define KPAD 40
#define AOFF 0
#define BOFF (128 * KPAD * 2)       // 10240
#define STGB (2 * 128 * KPAD * 2)   // 20480

__global__ void __launch_bounds__(256) conv_wmma_kernel(
    const bf16* __restrict__ A, const bf16* __restrict__ B,
    const float* __restrict__ bias, float scale, bf16* __restrict__ dst)
{
    extern __shared__ __align__(16) bf16 cs[];
    const uint32_t sb = smem_u32(cs);

    const int tid  = threadIdx.x;
    const int lane = tid & 31;
    const int warp = tid >> 5;
    const int wm   = warp & 3;
    const int wn   = warp >> 2;

    const int M0 = blockIdx.x * 128;
    const int o0 = blockIdx.y * 128;

    const int crow = tid >> 2, cseg = tid & 3;
    const bf16* pA = A + (size_t)(M0 + crow) * CC + cseg * 8;
    const bf16* pB = B + (size_t)(o0 + crow) * CC + cseg * 8;
    const uint32_t sdst = (crow * KPAD + cseg * 8) * 2;
    const uint32_t rstep = 64 * KPAD * 2;

    float acc[2][8][4];
#pragma unroll
    for (int mi = 0; mi < 2; mi++)
#pragma unroll
        for (int nf = 0; nf < 8; nf++)
#pragma unroll
            for (int k = 0; k < 4; k++) acc[mi][nf][k] = 0.f;

    const int lrow = lane & 15;
    const int lsel = (lane >> 4) * 8;

#pragma unroll
    for (int p = 0; p < 2; p++) {
        uint32_t so = sb + p * STGB + sdst;
#pragma unroll
        for (int r = 0; r < 2; r++) {
            const size_t go = (size_t)r * 64 * CC + p * 32;
            cpa16(so + AOFF + r * rstep, pA + go);
            cpa16(so + BOFF + r * rstep, pB + go);
        }
        asm volatile("cp.async.commit_group;");
    }

    for (int ch = 0; ch < 16; ch++) {
        if (ch + 2 < 16) {
            uint32_t so = sb + ((ch + 2) % 3) * STGB + sdst;
#pragma unroll
            for (int r = 0; r < 2; r++) {
                const size_t go = (size_t)r * 64 * CC + (ch + 2) * 32;
                cpa16(so + AOFF + r * rstep, pA + go);
                cpa16(so + BOFF + r * rstep, pB + go);
            }
            asm volatile("cp.async.commit_group;");
            asm volatile("cp.async.wait_group 2;");
        } else if (ch + 1 < 16) {
            asm volatile("cp.async.wait_group 1;");
        } else {
            asm volatile("cp.async.wait_group 0;");
        }
        __syncthreads();

        const uint32_t stb = sb + (ch % 3) * STGB;
#pragma unroll
        for (int ks = 0; ks < 2; ks++) {
            const int kc = ks * 16 + lsel;
            uint32_t a[2][4];
#pragma unroll
            for (int mi = 0; mi < 2; mi++)
                ldmx4(a[mi], stb + AOFF + ((wm * 32 + mi * 16 + lrow) * KPAD + kc) * 2);
#pragma unroll
            for (int np = 0; np < 4; np++) {
                uint32_t b[4];
                ldmx4(b, stb + BOFF + ((wn * 64 + np * 16 + lrow) * KPAD + kc) * 2);
#pragma unroll
                for (int mi = 0; mi < 2; mi++)
#pragma unroll
                    for (int hf = 0; hf < 2; hf++)
                        mma16816(acc[mi][np * 2 + hf], a[mi], b[hf], b[2 + hf]);
            }
        }
        __syncthreads();
    }

#pragma unroll
    for (int mi = 0; mi < 2; mi++) {
        const int m  = M0 + wm * 32 + mi * 16 + (lane >> 2);
        const int b  = m / HW;
        const int pp = m % HW;
#pragma unroll
        for (int nf = 0; nf < 8; nf++) {
            const int o = o0 + wn * 64 + nf * 8 + (lane & 3) * 2;
            const int h = o >> 6, d = o & 63;
            const float b0 = bias[o], b1 = bias[o + 1];
            size_t i0 = ((size_t)(b * NH + h) * HW + pp) * DD + d;
            size_t i1 = i0 + (size_t)8 * DD;
            *(bf162*)(dst + i0) = bf162{
                __float2bfloat16((acc[mi][nf][0] + b0) * scale),
                __float2bfloat16((acc[mi][nf][1] + b1) * scale)};
            *(bf162*)(dst + i1) = bf162{
                __float2bfloat16((acc[mi][nf][2] + b0) * scale),
                __float2bfloat16((acc[mi][nf][3] + b1) * scale)};
        }
    }
}

// ---------------------------------------------------------------------------
// Logits mma: C[96][96] = A[96][64] * B[96][64]^T, bf16, pitch 72.
// ---------------------------------------------------------------------------
#define PBF 72
#define ABUF 13824   // 96*72*2

__device__ __forceinline__ void logits_mma(
    uint32_t sb, uint32_t aOff, uint32_t bOff, int lane, int wm, int wn,
    float acc[3][3][4])
{
    const int l15 = lane & 15;
#pragma unroll
    for (int ks = 0; ks < 4; ks++) {
        const int kc = ks * 16;
        uint32_t a[3][4];
#pragma unroll
        for (int mt = 0; mt < 3; mt++)
            ldmx4(a[mt], sb + aOff +
                ((wm * 48 + mt * 16 + l15) * PBF + kc + (lane >> 4) * 8) * 2);
#pragma unroll
        for (int nt = 0; nt < 3; nt++) {
            uint32_t b[2];
            ldmx2(b, sb + bOff +
                ((wn * 24 + nt * 8 + (l15 & 7)) * PBF + kc + ((l15 >> 3) & 1) * 8) * 2);
#pragma unroll
            for (int mt = 0; mt < 3; mt++)
                mma16816(acc[mt][nt], a[mt], b[0], b[1]);
        }
    }
}

// Output mma: C[96][64] = A[96][96](pitch APITCH bf16) * B[96][64](pitch 72, trans)
#define PA 104

template <int APITCH>
__device__ __forceinline__ void probs_mma(
    uint32_t sb, uint32_t aOff, uint32_t gOff, int lane, int wm, int wn,
    float acc[3][2][4])
{
    const int l15 = lane & 15;
#pragma unroll
    for (int ks = 0; ks < 6; ks++) {
        const int kc = ks * 16;
        uint32_t a[3][4];
#pragma unroll
        for (int mt = 0; mt < 3; mt++)
            ldmx4(a[mt], sb + aOff +
                ((wm * 48 + mt * 16 + l15) * APITCH + kc + (lane >> 4) * 8) * 2);
        uint32_t bt[4];
        ldmxt4(bt, sb + gOff + ((kc + l15) * PBF + wn * 16 + (lane >> 4) * 8) * 2);
#pragma unroll
        for (int mt = 0; mt < 3; mt++) {
            mma16816(acc[mt][0], a[mt], bt[0], bt[1]);
            mma16816(acc[mt][1], a[mt], bt[2], bt[3]);
        }
    }
}

// ---------------------------------------------------------------------------
// Kernel 2: row logits -> d_Er. Block (y, bh).
// ---------------------------------------------------------------------------
__global__ void __launch_bounds__(256) erow_kernel()
{
    extern __shared__ __align__(16) char smem[];
    const uint32_t sb = smem_u32(smem);

    const int y = blockIdx.x, bh = blockIdx.y, tid = threadIdx.x;
    const int lane = tid & 31, warp = tid >> 5;

    const size_t off = ((size_t)bh * HW + y * 96) * DD;
    const bf16* srcs[2] = {d_tb + off, d_fb + off};
#pragma unroll
    for (int a = 0; a < 2; a++)
#pragma unroll
        for (int k = 0; k < 3; k++) {
            int idx = tid + k * 256;
            int row = idx >> 3, c = (idx & 7) * 8;
            *(uint4*)(smem + a * ABUF + (row * PBF + c) * 2) =
                *(const uint4*)(srcs[a] + (size_t)idx * 8);
        }
    __syncthreads();

    float acc[3][3][4];
#pragma unroll
    for (int mt = 0; mt < 3; mt++)
#pragma unroll
        for (int nt = 0; nt < 3; nt++)
#pragma unroll
            for (int k = 0; k < 4; k++) acc[mt][nt][k] = 0.f;

    const int wm = warp >> 2, wn = warp & 3;
    logits_mma(sb, 0, ABUF, lane, wm, wn, acc);

    float* Eb = d_Er + ((size_t)bh * HH + y) * WW * 96;
#pragma unroll
    for (int mt = 0; mt < 3; mt++)
#pragma unroll
        for (int nt = 0; nt < 3; nt++) {
            const int x0 = wm * 48 + mt * 16 + (lane >> 2);
            const int i0 = wn * 24 + nt * 8 + (lane & 3) * 2;
            *(float2*)&Eb[(size_t)x0 * 96 + i0]       = float2{acc[mt][nt][0], acc[mt][nt][1]};
            *(float2*)&Eb[(size_t)(x0 + 8) * 96 + i0] = float2{acc[mt][nt][2], acc[mt][nt][3]};
        }
}

// ---------------------------------------------------------------------------
// Kernel 3 (fused): per (x, bh): col logits (mma, SMEM) + softmax(192)
//   with direct prob emission + column output (mma) -> d_O.
// SMEM phases:
//   P1: t@0, f@13824 (27648) | Ec f32 [96][100] @38400 (38400)
//   P2: Er f32 [96][100] @0 | g bf16 [96][72] @76800 (13824)
//   P3: Acol bf16 [96] pitch 200 bf16 (400 B) @0 — in-place over Er rows:
//       warp w's Ac[r] write (192 B) stays inside Er[r]'s own 400-B row,
//       which only warp w reads (and reads precede the write per iteration).
// total 90624 B
// ---------------------------------------------------------------------------
#define EC_OFF 38400
#define G_OFF  76800
#define PAC 200   // Ac pitch in bf16 (= Er row pitch of 400 B)

__global__ void __launch_bounds__(256) fusedcol_kernel()
{
    extern __shared__ __align__(16) char smem[];
    const uint32_t sb = smem_u32(smem);

    const int x = blockIdx.x, bh = blockIdx.y, tid = threadIdx.x;
    const int lane = tid & 31, warp = tid >> 5;
    const int wm = warp >> 2, wn = warp & 3;

    // P1 load: t/f columns (row stride WW*DD)
    {
        const size_t off = ((size_t)bh * HW + x) * DD;
        const bf16* srcs[2] = {d_tb + off, d_fb + off};
#pragma unroll
        for (int a = 0; a < 2; a++)
#pragma unroll
            for (int k = 0; k < 3; k++) {
                int idx = tid + k * 256;
                int row = idx >> 3, c = (idx & 7) * 8;
                *(uint4*)(smem + a * ABUF + (row * PBF + c) * 2) =
                    *(const uint4*)(srcs[a] + (size_t)row * (WW * DD) + c);
            }
    }
    __syncthreads();

    // column logits -> Ec with diagonal mask
    {
        float acc[3][3][4];
#pragma unroll
        for (int mt = 0; mt < 3; mt++)
#pragma unroll
            for (int nt = 0; nt < 3; nt++)
#pragma unroll
                for (int k = 0; k < 4; k++) acc[mt][nt][k] = 0.f;

        logits_mma(sb, 0, ABUF, lane, wm, wn, acc);

        float (*Ec)[100] = (float(*)[100])(smem + EC_OFF);
#pragma unroll
        for (int mt = 0; mt < 3; mt++)
#pragma unroll
            for (int nt = 0; nt < 3; nt++) {
                const int y0 = wm * 48 + mt * 16 + (lane >> 2);
                const int i0 = wn * 24 + nt * 8 + (lane & 3) * 2;
                Ec[y0][i0]     = (i0     == y0)     ? -INFINITY : acc[mt][nt][0];
                Ec[y0][i0 + 1] = (i0 + 1 == y0)     ? -INFINITY : acc[mt][nt][1];
                Ec[y0 + 8][i0]     = (i0     == y0 + 8) ? -INFINITY : acc[mt][nt][2];
                Ec[y0 + 8][i0 + 1] = (i0 + 1 == y0 + 8) ? -INFINITY : acc[mt][nt][3];
            }
    }
    __syncthreads();   // t/f reads done, Ec complete

    // P2 loads: Er slice + g column
    {
        float (*Er)[100] = (float(*)[100])smem;
        const float* eb = d_Er + (size_t)bh * HH * WW * 96 + (size_t)x * 96;
        for (int idx = tid; idx < 96 * 24; idx += 256) {
            int r = idx / 24, c4 = idx % 24;
            *(float4*)&Er[r][c4 * 4] =
                *(const float4*)(eb + (size_t)r * (WW * 96) + c4 * 4);
        }
        const bf16* gsrc = d_gb + ((size_t)bh * HW + x) * DD;
#pragma unroll
        for (int k = 0; k < 3; k++) {
            int idx = tid + k * 256;
            int row = idx >> 3, c = (idx & 7) * 8;
            *(uint4*)(smem + G_OFF + (row * PBF + c) * 2) =
                *(const uint4*)(gsrc + (size_t)row * (WW * DD) + c);
        }
    }
    __syncthreads();

    // softmax over concat(Er, Ec) — warp per row; emits probs directly:
    // row probs -> d_Ar (gmem bf16), col probs -> Ac smem (pitch 400 B,
    // in place over this row's own Er storage; no cross-warp overlap)
    {
        float (*Er)[100] = (float(*)[100])smem;
        float (*Ec)[100] = (float(*)[100])(smem + EC_OFF);
        bf16* Ac = (bf16*)smem;
#pragma unroll 1
        for (int rr = 0; rr < 12; rr++) {
            const int r = warp * 12 + rr;
            float vr[3], vc[3];
#pragma unroll
            for (int k = 0; k < 3; k++) { vr[k] = Er[r][lane + k * 32]; vc[k] = Ec[r][lane + k * 32]; }
            float m = -INFINITY;
#pragma unroll
            for (int k = 0; k < 3; k++) m = fmaxf(m, fmaxf(vr[k], vc[k]));
#pragma unroll
            for (int off = 16; off; off >>= 1) m = fmaxf(m, __shfl_xor_sync(0xffffffffu, m, off));
            float s = 0.f;
#pragma unroll
            for (int k = 0; k < 3; k++) {
                vr[k] = __expf(vr[k] - m); vc[k] = __expf(vc[k] - m);
                s += vr[k] + vc[k];
            }
#pragma unroll
            for (int off = 16; off; off >>= 1) s += __shfl_xor_sync(0xffffffffu, s, off);
            const float inv = 1.f / s;
            bf16* arow = d_Ar + ((size_t)(bh * HH + r) * WW + x) * 96;
            bf16* acrow = Ac + r * PAC;
#pragma unroll
            for (int k = 0; k < 3; k++) {
                arow[lane + k * 32]  = __float2bfloat16(vr[k] * inv);
                acrow[lane + k * 32] = __float2bfloat16(vc[k] * inv);
            }
        }
    }
    __syncthreads();

    // column output mma -> d_O
    {
        float acc[3][2][4];
#pragma unroll
        for (int mt = 0; mt < 3; mt++)
#pragma unroll
            for (int nt = 0; nt < 2; nt++)
#pragma unroll
                for (int k = 0; k < 4; k++) acc[mt][nt][k] = 0.f;

        probs_mma<PAC>(sb, 0, G_OFF, lane, wm, wn, acc);

#pragma unroll
        for (int mt = 0; mt < 3; mt++)
#pragma unroll
            for (int nt = 0; nt < 2; nt++) {
                const int yv = wm * 48 + mt * 16 + (lane >> 2);
                const int d0 = wn * 16 + nt * 8 + (lane & 3) * 2;
                float* ob = d_O + ((size_t)(bh * HH + yv) * WW + x) * DD + d0;
                *(float2*)ob = float2{acc[mt][nt][0], acc[mt][nt][1]};
                *(float2*)(ob + (size_t)8 * WW * DD) = float2{acc[mt][nt][2], acc[mt][nt][3]};
            }
    }
}

// ---------------------------------------------------------------------------
// Kernel 4: row output (mma) + combine + residual. Block (y, bh).
// ---------------------------------------------------------------------------
__global__ void __launch_bounds__(256) rowout_kernel(
    const float* __restrict__ v, const float* __restrict__ gamma,
    float* __restrict__ out)
{
    __shared__ __align__(16) bf16 Asm[96][PA];
    __shared__ __align__(16) bf16 gsm[96][PBF];

    const int y = blockIdx.x, bh = blockIdx.y, tid = threadIdx.x;
    const int lane = tid & 31, warp = tid >> 5;
    const int wm = warp >> 2, wn = warp & 3;

    const bf16* ab = d_Ar + ((size_t)bh * HH + y) * WW * 96;
    for (int idx = tid; idx < 96 * 12; idx += 256) {
        int row = idx / 12, c8 = idx % 12;
        *(uint4*)&Asm[row][c8 * 8] = *(const uint4*)(ab + (size_t)row * 96 + c8 * 8);
    }
    const bf16* gb = d_gb + ((size_t)bh * HH + y) * WW * DD;
#pragma unroll
    for (int k = 0; k < 3; k++) {
        int idx = tid + k * 256;
        int row = idx >> 3, c = (idx & 7) * 8;
        *(uint4*)&gsm[row][c] = *(const uint4*)(gb + (size_t)idx * 8);
    }
    __syncthreads();

    float acc[3][2][4];
#pragma unroll
    for (int mt = 0; mt < 3; mt++)
#pragma unroll
        for (int nt = 0; nt < 2; nt++)
#pragma unroll
            for (int k = 0; k < 4; k++) acc[mt][nt][k] = 0.f;

    const uint32_t sbA = smem_u32(Asm);
    const uint32_t sbG = smem_u32(gsm);
    probs_mma<PA>(sbA, 0, sbG - sbA, lane, wm, wn, acc);

    const float gam = gamma[0];
    const int b = bh >> 3, h = bh & 7;
    const float* colp = d_O + ((size_t)bh * HH + y) * WW * DD;

#pragma unroll
    for (int mt = 0; mt < 3; mt++)
#pragma unroll
        for (int nt = 0; nt < 2; nt++) {
            const int x0 = wm * 48 + mt * 16 + (lane >> 2);
            const int d0 = wn * 16 + nt * 8 + (lane & 3) * 2;
#pragma unroll
            for (int rh = 0; rh < 2; rh++) {
                const int xx = x0 + rh * 8;
                float2 cp = *(const float2*)(colp + (size_t)xx * DD + d0);
                float s0 = acc[mt][nt][rh * 2]     + cp.x;
                float s1 = acc[mt][nt][rh * 2 + 1] + cp.y;
                size_t oa0 = (((size_t)(b * CC + h * 64 + d0)) * HH + y) * WW + xx;
                size_t oa1 = oa0 + (size_t)HW;
                out[oa0] = gam * s0 + v[oa0];
                out[oa1] = gam * s1 + v[oa1];
            }
        }
}

// ---------------------------------------------------------------------------
extern "C" void kernel_launch(void* const* d_in, const int* in_sizes, int n_in,
                              void* d_out, int out_size)
{
    const float* q     = (const float*)d_in[0];
    const float* v     = (const float*)d_in[1];
    const float* Wq    = (const float*)d_in[2];
    const float* bq    = (const float*)d_in[3];
    const float* Wk    = (const float*)d_in[4];
    const float* bk    = (const float*)d_in[5];
    const float* Wv    = (const float*)d_in[6];
    const float* bv    = (const float*)d_in[7];
    const float* gamma = (const float*)d_in[8];
    float* out = (float*)d_out;

    static bf16 *pAq = nullptr, *pAv, *pW, *pT, *pF, *pG;
    static cudaStream_t s2;
    static cudaEvent_t evFork, evJoin;
    if (!pAq) {
        cudaGetSymbolAddress((void**)&pAq, d_Aq);
        cudaGetSymbolAddress((void**)&pAv, d_Av);
        cudaGetSymbolAddress((void**)&pW,  d_W);
        cudaGetSymbolAddress((void**)&pT,  d_tb);
        cudaGetSymbolAddress((void**)&pF,  d_fb);
        cudaGetSymbolAddress((void**)&pG,  d_gb);
        cudaStreamCreateWithFlags(&s2, cudaStreamNonBlocking);
        cudaEventCreateWithFlags(&evFork, cudaEventDisableTiming);
        cudaEventCreateWithFlags(&evJoin, cudaEventDisableTiming);
    }

    const int smConv = 3 * STGB;     // 61440
    const int smE    = 2 * ABUF;     // 27648
    const int smF    = G_OFF + ABUF; // 90624
    static bool attrs_set = false;
    if (!attrs_set) {
        cudaFuncSetAttribute(conv_wmma_kernel, cudaFuncAttributeMaxDynamicSharedMemorySize, smConv);
        cudaFuncSetAttribute(erow_kernel,      cudaFuncAttributeMaxDynamicSharedMemorySize, smE);
        cudaFuncSetAttribute(fusedcol_kernel,  cudaFuncAttributeMaxDynamicSharedMemorySize, smF);
        attrs_set = true;
    }

    // Prepasses (merged launches)
    dim3 spGrid(HW / 32, CC / 32, 2 * BB);
    toA_kernel<<<spGrid, 256>>>(q, v, pAq, pAv);
    dim3 wGrid((CC * CC + 255) / 256, 3);
    toW_kernel<<<wGrid, 256>>>(Wq, Wk, Wv, pW);

    // Conv GEMMs: t, f on main stream
    dim3 cg(MTOT / 128, CC / 128);
    conv_wmma_kernel<<<cg, 256, smConv>>>(pAq, pW,          bq, SCALING, pT);
    conv_wmma_kernel<<<cg, 256, smConv>>>(pAq, pW + CC * CC, bk, 1.0f,    pF);

    // Fork: conv-g (tensor-bound) overlaps erow (memory-bound)
    cudaEventRecord(evFork, 0);
    cudaStreamWaitEvent(s2, evFork, 0);
    conv_wmma_kernel<<<cg, 256, smConv, s2>>>(pAv, pW + 2 * CC * CC, bv, 1.0f, pG);

    dim3 attnGrid(96, BHD);
    erow_kernel<<<attnGrid, 256, smE>>>();

    cudaEventRecord(evJoin, s2);
    cudaStreamWaitEvent(0, evJoin, 0);

    // Remaining attention
    fusedcol_kernel<<<attnGrid, 256, smF>>>();
    rowout_kernel<<<attnGrid, 256>>>(v, gamma, out);
}